// round 10
// baseline (speedup 1.0000x reference)
#include <cuda_runtime.h>
#include <cuda_fp16.h>
#include <cstdint>

// ---------------- problem constants (registry shapes) ----------------
#define NN      10000          // nodes per graph
#define EMAXE   320000         // edges (without self loops)
#define E2MAX   (EMAXE + NN)   // + self loops
#define BBMAX   4              // batch
#define DEGCAP  128            // padded-CSR capacity (max degree ~60 => 12 sigma safe)

// ---------------- device scratch (no allocations allowed) -------------
__device__ int   g_esrc[NN * DEGCAP];   // padded CSR: src per slot
__device__ int   g_count[NN];
__device__ int   g_is64;
__device__ float g_h0 [BBMAX * NN * 256];   // layer0 pre-attention features (fp32)
__device__ float g_h1 [BBMAX * NN * 128];   // layer1 pre-attention features (fp32)
__device__ __half g_h0x[BBMAX * NN * 256];  // fp16 copies for the agg gather
__device__ __half g_h1x[BBMAX * NN * 128];
__device__ float g_als[BBMAX * NN];
__device__ float g_ald[BBMAX * NN];
// fp16 operands: x split hi/lo (exact to ~2^-22), W single fp16 (err 2^-12)
__device__ __half g_xh [BBMAX * NN * 256];
__device__ __half g_xl [BBMAX * NN * 256];
__device__ __half g_hidh[BBMAX * NN * 256];  // layer0 output, split
__device__ __half g_hidl[BBMAX * NN * 256];
__device__ __half g_w0 [256 * 256];
__device__ __half g_w1 [128 * 256];

// ---------------- edge preprocessing ----------------------------------

// fused: all blocks zero counts; block 0 lane 0 also detects int64 vs int32
__global__ void zerodetect_kernel(const unsigned int* __restrict__ w, int n) {
    int i = blockIdx.x * blockDim.x + threadIdx.x;
    if (i < n) g_count[i] = 0;
    if (blockIdx.x == 0 && threadIdx.x == 0) {
        int ok = 1;
        for (int k = 1; k < 256; k += 2) {
            if (w[k] != 0u) { ok = 0; break; }
        }
        g_is64 = ok;
    }
}

// one-pass padded-CSR build (incl. self loops)
__global__ void convert_scatter_kernel(const void* __restrict__ edges, int E, int Nn) {
    int i = blockIdx.x * blockDim.x + threadIdx.x;
    int E2 = E + Nn;
    if (i >= E2) return;
    int s, d;
    if (i < E) {
        if (g_is64) {
            const long long* p = (const long long*)edges;
            s = (int)p[i];
            d = (int)p[E + i];
        } else {
            const int* p = (const int*)edges;
            s = p[i];
            d = p[E + i];
        }
    } else {
        s = d = i - E;
    }
    int pos = atomicAdd(&g_count[d], 1);
    g_esrc[d * DEGCAP + pos] = s;
}

// ---------------- fused splits / quantize (x hi/lo, W0, W1) ------------
__global__ void split3_kernel(const float* __restrict__ s0, __half* h0p, __half* l0p, int n0,
                              const float* __restrict__ s1, __half* h1p, int n1,
                              const float* __restrict__ s2, __half* h2p, int n2) {
    int i = blockIdx.x * blockDim.x + threadIdx.x;
    if (i < n0) {
        float4 v = ((const float4*)s0)[i];
        float f[4] = {v.x, v.y, v.z, v.w};
        __half h[4], l[4];
#pragma unroll
        for (int q = 0; q < 4; q++) {
            h[q] = __float2half(f[q]);
            l[q] = __float2half(f[q] - __half2float(h[q]));
        }
        ((uint2*)h0p)[i] = *(uint2*)h;
        ((uint2*)l0p)[i] = *(uint2*)l;
        return;
    }
    i -= n0;
    const float* src; __half* ph;
    if (i < n1)              { src = s1; ph = h1p; }
    else if ((i -= n1) < n2) { src = s2; ph = h2p; }
    else return;
    float4 v = ((const float4*)src)[i];
    __half h[4] = {__float2half(v.x), __float2half(v.y),
                   __float2half(v.z), __float2half(v.w)};
    ((uint2*)ph)[i] = *(uint2*)h;
}

// ---------------- fp16 two-term tensor-core GEMM -----------------------
// C[M][N] = A[M][K] * W[N][K]^T; A pre-split fp16 hi/lo, W single fp16;
// acc += hi*W; acc += lo*W (fp32 accum). Epilogue writes fp32 C + fp16 Cx.

#define MMA16(c, a, b)                                                        \
    asm volatile(                                                             \
        "mma.sync.aligned.m16n8k16.row.col.f32.f16.f16.f32 "                  \
        "{%0,%1,%2,%3},{%4,%5,%6,%7},{%8,%9},{%0,%1,%2,%3};"                  \
        : "+f"((c)[0]), "+f"((c)[1]), "+f"((c)[2]), "+f"((c)[3])              \
        : "r"((a)[0]), "r"((a)[1]), "r"((a)[2]), "r"((a)[3]),                 \
          "r"((b)[0]), "r"((b)[1]))

#define LDSM4(R, addr)                                                        \
    asm volatile(                                                             \
        "ldmatrix.sync.aligned.m8n8.x4.shared.b16 {%0,%1,%2,%3}, [%4];"       \
        : "=r"((R)[0]), "=r"((R)[1]), "=r"((R)[2]), "=r"((R)[3])              \
        : "r"(addr))

#define CPA16(dst, src, sz)                                                   \
    asm volatile("cp.async.cg.shared.global [%0], [%1], 16, %2;"              \
                 :: "r"(dst), "l"(src), "r"(sz) : "memory")
#define CPA_COMMIT() asm volatile("cp.async.commit_group;" ::: "memory")
#define CPA_WAIT1()  asm volatile("cp.async.wait_group 1;" ::: "memory")
#define CPA_WAIT0()  asm volatile("cp.async.wait_group 0;" ::: "memory")

#define GEMM_AP    24                     // padded row (fp16): LDSM conflict-free
#define GEMM_ARRB  (128 * GEMM_AP * 2)    // bytes per array image (6144)
#define GEMM_BUFB  (3 * GEMM_ARRB)        // bytes per stage (Ah, Al, B)
#define GEMM_SMEM  (3 * GEMM_BUFB)        // 3-stage ring = 55296 B

__global__ __launch_bounds__(256, 2)
void gemm_fp16_kernel(const __half* __restrict__ Ah,
                      const __half* __restrict__ Al,
                      const __half* __restrict__ Bw,
                      float* __restrict__ C, __half* __restrict__ Cx,
                      int M, int N, int K) {
    constexpr int BK = 16;
    constexpr int AP = GEMM_AP;
    extern __shared__ __half sm[];

    int tid  = threadIdx.x;
    int wid  = tid >> 5;
    int lane = tid & 31;
    int wm0  = (wid >> 1) * 32;         // 4x2 warp grid, warp tile 32x64
    int wn0  = (wid & 1) * 64;
    int g    = lane >> 2;
    int tg   = lane & 3;
    int m0   = blockIdx.y * 128;
    int n0   = blockIdx.x * 128;

    float acc[2][8][4];
#pragma unroll
    for (int mt = 0; mt < 2; mt++)
#pragma unroll
        for (int nt = 0; nt < 8; nt++)
#pragma unroll
            for (int j = 0; j < 4; j++) acc[mt][nt][j] = 0.f;

    // ldmatrix per-lane offsets (fp16 elements within a tile image)
    int a_off = (wm0 + (lane & 15)) * AP + ((lane >> 4) << 3);
    int bq = lane >> 3, br = lane & 7;
    int b_off = (wn0 + ((bq >> 1) << 3) + br) * AP + ((bq & 1) << 3);

    // cp.async staging: 1 item (16B) per thread per array
    int r0 = tid >> 1, s0g = tid & 1;
    unsigned sz0a = (m0 + r0 < M) ? 16u : 0u;
    size_t ar0 = (size_t)min(m0 + r0, M - 1) * K + s0g * 8;
    size_t br0 = (size_t)(n0 + r0) * K + s0g * 8;
    unsigned d0 = (unsigned)(r0 * 48 + s0g * 16);

    unsigned smb = (unsigned)__cvta_generic_to_shared(sm);

    auto stage = [&](int buf, int koff) {
        unsigned b = smb + buf * GEMM_BUFB;
        CPA16(b + 0 * GEMM_ARRB + d0, Ah + ar0 + koff, sz0a);
        CPA16(b + 1 * GEMM_ARRB + d0, Al + ar0 + koff, sz0a);
        CPA16(b + 2 * GEMM_ARRB + d0, Bw + br0 + koff, 16u);
        CPA_COMMIT();
    };

    int nk = K / BK;
    stage(0, 0);
    stage(1, BK);

    for (int t = 0; t < nk; ++t) {
        CPA_WAIT1();                    // stage t complete
        __syncthreads();                // all warps done with buf (t-1)%3
        if (t + 2 < nk) stage((t + 2) % 3, (t + 2) * BK);

        unsigned abase = smb + (t % 3) * GEMM_BUFB;
        unsigned ah[2][4], alr[2][4];
#pragma unroll
        for (int mt = 0; mt < 2; mt++) {
            LDSM4(ah[mt],  abase + 0 * GEMM_ARRB + (a_off + mt * 16 * AP) * 2);
            LDSM4(alr[mt], abase + 1 * GEMM_ARRB + (a_off + mt * 16 * AP) * 2);
        }
#pragma unroll
        for (int half = 0; half < 2; half++) {
            unsigned bf[2][4];
#pragma unroll
            for (int p = 0; p < 2; p++) {
                unsigned boff = (b_off + (half * 32 + p * 16) * AP) * 2;
                LDSM4(bf[p], abase + 2 * GEMM_ARRB + boff);
            }
#pragma unroll
            for (int mt = 0; mt < 2; mt++)
#pragma unroll
                for (int ntl = 0; ntl < 4; ntl++) {
                    int nt = half * 4 + ntl;
                    MMA16(acc[mt][nt], ah[mt],  &bf[ntl >> 1][(ntl & 1) * 2]);
                    MMA16(acc[mt][nt], alr[mt], &bf[ntl >> 1][(ntl & 1) * 2]);
                }
        }
    }
    CPA_WAIT0();

    // epilogue: fp32 C (for al) + fp16 Cx (for agg gather)
#pragma unroll
    for (int mt = 0; mt < 2; mt++) {
        int r = m0 + wm0 + mt * 16 + g;
#pragma unroll
        for (int nt = 0; nt < 8; nt++) {
            int col = n0 + wn0 + nt * 8 + 2 * tg;
            if (r < M) {
                *(float2*)(C + (size_t)r * N + col) =
                    make_float2(acc[mt][nt][0], acc[mt][nt][1]);
                *(__half2*)(Cx + (size_t)r * N + col) =
                    __floats2half2_rn(acc[mt][nt][0], acc[mt][nt][1]);
            }
            if (r + 8 < M) {
                *(float2*)(C + (size_t)(r + 8) * N + col) =
                    make_float2(acc[mt][nt][2], acc[mt][nt][3]);
                *(__half2*)(Cx + (size_t)(r + 8) * N + col) =
                    __floats2half2_rn(acc[mt][nt][2], acc[mt][nt][3]);
            }
        }
    }
}

// ---------------- attention-logit dot products (fp32 h) ----------------
template <int F>
__global__ void al_kernel(const float* __restrict__ h, const float* __restrict__ asrc,
                          const float* __restrict__ adst, float* __restrict__ als,
                          float* __restrict__ ald, int M) {
    int warp = (blockIdx.x * blockDim.x + threadIdx.x) >> 5;
    int lane = threadIdx.x & 31;
    if (warp >= M) return;
    const float* row = h + (size_t)warp * F;
    float s = 0.f, d = 0.f;
#pragma unroll
    for (int i = lane; i < F; i += 32) {
        float v = row[i];
        s += v * asrc[i];
        d += v * adst[i];
    }
#pragma unroll
    for (int o = 16; o; o >>= 1) {
        s += __shfl_xor_sync(0xffffffffu, s, o);
        d += __shfl_xor_sync(0xffffffffu, d, o);
    }
    if (!lane) {
        als[warp] = s;
        ald[warp] = d;
    }
}

// ---------------- softmax aggregation (one block per (batch,dst)) ------
// Gather from fp16 h copy: 8 edges in flight, uint4 (8 halves) per thread.
template <int F, bool SPLIT>
__global__ __launch_bounds__(F)
void agg_kernel(const __half* __restrict__ hx, const float* __restrict__ als,
                const float* __restrict__ ald, const float* __restrict__ bias,
                float* __restrict__ out,
                __half* __restrict__ outh, __half* __restrict__ outl,
                int Nn) {
    constexpr int NW = F / 32;
    constexpr int FO = F / 8;           // threads per edge group (8-feature octs)
    __shared__ float sred[NW];
    __shared__ float sbc;
    __shared__ float sw[DEGCAP + 8];
    __shared__ int   ssrc[DEGCAP + 8];
    __shared__ float sredf[8][FO][8];

    int bx   = blockIdx.x;
    int v    = bx % Nn;
    int b    = bx / Nn;
    int tid  = threadIdx.x;
    int lane = tid & 31;
    int w    = tid >> 5;
    int begin = v * DEGCAP;
    int deg   = g_count[v];
    int base  = b * Nn;
    float aldv = ald[base + v];

    // pass 1a: segment max
    float lm = -1e30f;
    for (int j = tid; j < deg; j += F) {
        float e = als[base + g_esrc[begin + j]] + aldv;
        e = (e < 0.f) ? 0.2f * e : e;
        lm = fmaxf(lm, e);
    }
#pragma unroll
    for (int o = 16; o; o >>= 1) lm = fmaxf(lm, __shfl_xor_sync(0xffffffffu, lm, o));
    if (!lane) sred[w] = lm;
    __syncthreads();
    if (w == 0) {
        float x = (lane < NW) ? sred[lane] : -1e30f;
#pragma unroll
        for (int o = 16; o; o >>= 1) x = fmaxf(x, __shfl_xor_sync(0xffffffffu, x, o));
        if (!lane) sbc = x;
    }
    __syncthreads();
    float m = sbc;

    // pass 1b: denominator + stash per-edge exp weights in shared
    float ls = 0.f;
    for (int j = tid; j < deg; j += F) {
        int s = g_esrc[begin + j];
        float e = als[base + s] + aldv;
        e = (e < 0.f) ? 0.2f * e : e;
        float ex = __expf(e - m);
        ssrc[j] = s;
        sw[j]   = ex;
        ls += ex;
    }
    if (tid < 8) {                      // zero-pad to multiple of 8
        int j = deg + tid;
        sw[j] = 0.f;
        ssrc[j] = 0;
    }
#pragma unroll
    for (int o = 16; o; o >>= 1) ls += __shfl_xor_sync(0xffffffffu, ls, o);
    if (!lane) sred[w] = ls;
    __syncthreads();
    if (w == 0) {
        float x = (lane < NW) ? sred[lane] : 0.f;
#pragma unroll
        for (int o = 16; o; o >>= 1) x += __shfl_xor_sync(0xffffffffu, x, o);
        if (!lane) sbc = x;
    }
    __syncthreads();
    float inv = 1.f / (sbc + 1e-16f);

    // pass 2: fp16 gather — edge group eg (8 in flight), feature oct fq
    int eg = tid / FO;
    int fq = tid % FO;
    float a8[8];
#pragma unroll
    for (int q = 0; q < 8; q++) a8[q] = 0.f;
    for (int j0 = 0; j0 < deg; j0 += 8) {
        int j = j0 + eg;                // always staged (zero-padded)
        float wj = sw[j];
        uint4 hv = *(const uint4*)(hx + (size_t)(base + ssrc[j]) * F + fq * 8);
        const __half2* hp = (const __half2*)&hv;
#pragma unroll
        for (int q = 0; q < 4; q++) {
            float2 f2 = __half22float2(hp[q]);
            a8[q * 2 + 0] += wj * f2.x;
            a8[q * 2 + 1] += wj * f2.y;
        }
    }
#pragma unroll
    for (int q = 0; q < 8; q++) sredf[eg][fq][q] = a8[q];
    __syncthreads();

    int qo = tid >> 3, c = tid & 7;
    float r = 0.f;
#pragma unroll
    for (int gq = 0; gq < 8; gq++) r += sredf[gq][qo][c];
    r = r * inv + bias[tid];
    r = r > 0.f ? r : 0.f;
    size_t oi = (size_t)(base + v) * F + tid;
    if (SPLIT) {
        __half hi = __float2half(r);
        __half lo = __float2half(r - __half2float(hi));
        outh[oi] = hi;
        outl[oi] = lo;
    } else {
        out[oi] = r;
    }
}

// ---------------- launch ----------------------------------------------
extern "C" void kernel_launch(void* const* d_in, const int* in_sizes, int n_in,
                              void* d_out, int out_size) {
    const float* x     = (const float*)d_in[0];
    const void*  edges = d_in[1];
    const float* W0    = (const float*)d_in[2];
    const float* b0    = (const float*)d_in[3];
    const float* asrc0 = (const float*)d_in[4];
    const float* adst0 = (const float*)d_in[5];
    const float* W1    = (const float*)d_in[6];
    const float* b1    = (const float*)d_in[7];
    const float* asrc1 = (const float*)d_in[8];
    const float* adst1 = (const float*)d_in[9];
    float* out = (float*)d_out;

    int F1 = in_sizes[3];            // 256
    int F0 = in_sizes[2] / F1;       // 256
    int F2 = in_sizes[7];            // 128
    int E  = in_sizes[1] / 2;        // 320000
    int M  = in_sizes[0] / F0;       // B*N = 40000
    int Nn = NN;                     // 10000
    int E2 = E + Nn;

    float *p_h0, *p_h1, *p_als, *p_ald;
    __half *p_h0x, *p_h1x, *p_xh, *p_xl, *p_hidh, *p_hidl, *p_w0, *p_w1;
    cudaGetSymbolAddress((void**)&p_h0,   g_h0);
    cudaGetSymbolAddress((void**)&p_h1,   g_h1);
    cudaGetSymbolAddress((void**)&p_h0x,  g_h0x);
    cudaGetSymbolAddress((void**)&p_h1x,  g_h1x);
    cudaGetSymbolAddress((void**)&p_als,  g_als);
    cudaGetSymbolAddress((void**)&p_ald,  g_ald);
    cudaGetSymbolAddress((void**)&p_xh,   g_xh);
    cudaGetSymbolAddress((void**)&p_xl,   g_xl);
    cudaGetSymbolAddress((void**)&p_hidh, g_hidh);
    cudaGetSymbolAddress((void**)&p_hidl, g_hidl);
    cudaGetSymbolAddress((void**)&p_w0,   g_w0);
    cudaGetSymbolAddress((void**)&p_w1,   g_w1);

    cudaFuncSetAttribute(gemm_fp16_kernel,
                         cudaFuncAttributeMaxDynamicSharedMemorySize, GEMM_SMEM);

    int mtiles = (M + 127) / 128;
    int n0q = M * F0 / 4, n1q = F1 * F0 / 4, n2q = F2 * F1 / 4;

    // (0) fused splits, (1) zero+detect, (2) CSR build, (3) GEMM0 [profiled]
    split3_kernel<<<(n0q + n1q + n2q + 255) / 256, 256>>>(
        x, p_xh, p_xl, n0q, W0, p_w0, n1q, W1, p_w1, n2q);
    zerodetect_kernel<<<(Nn + 255) / 256, 256>>>((const unsigned int*)edges, Nn);
    convert_scatter_kernel<<<(E2 + 255) / 256, 256>>>(edges, E, Nn);

    gemm_fp16_kernel<<<dim3(F1 / 128, mtiles), 256, GEMM_SMEM>>>(
        p_xh, p_xl, p_w0, p_h0, p_h0x, M, F1, F0);
    al_kernel<256><<<(M * 32 + 255) / 256, 256>>>(p_h0, asrc0, adst0, p_als, p_ald, M);
    agg_kernel<256, true><<<M, 256>>>(p_h0x, p_als, p_ald, b0,
                                      nullptr, p_hidh, p_hidl, Nn);

    gemm_fp16_kernel<<<dim3(F2 / 128, mtiles), 256, GEMM_SMEM>>>(
        p_hidh, p_hidl, p_w1, p_h1, p_h1x, M, F2, F1);
    al_kernel<128><<<(M * 32 + 255) / 256, 256>>>(p_h1, asrc1, adst1, p_als, p_ald, M);
    agg_kernel<128, false><<<M, 128>>>(p_h1x, p_als, p_ald, b1,
                                       out, nullptr, nullptr, Nn);
}

// round 11
// speedup vs baseline: 1.2258x; 1.2258x over previous
#include <cuda_runtime.h>
#include <cuda_fp16.h>
#include <cstdint>

// ---------------- problem constants (registry shapes) ----------------
#define NN      10000          // nodes per graph
#define EMAXE   320000         // edges (without self loops)
#define E2MAX   (EMAXE + NN)   // + self loops
#define BBMAX   4              // batch
#define DEGCAP  128            // padded-CSR capacity (max degree ~60 => 12 sigma safe)

// ---------------- device scratch (no allocations allowed) -------------
__device__ int   g_esrc[NN * DEGCAP];   // padded CSR: src per slot
__device__ int   g_count[NN];
__device__ int   g_is64;
__device__ float g_h0 [BBMAX * NN * 256];   // layer0 pre-attention features (fp32)
__device__ float g_h1 [BBMAX * NN * 128];   // layer1 pre-attention features (fp32)
__device__ __half g_h0x[BBMAX * NN * 256];  // fp16 copies for the agg gather
__device__ __half g_h1x[BBMAX * NN * 128];
__device__ float g_als[BBMAX * NN];
__device__ float g_ald[BBMAX * NN];
// fp16 operands: x split hi/lo (exact to ~2^-22), W single fp16 (err 2^-12)
__device__ __half g_xh [BBMAX * NN * 256];
__device__ __half g_xl [BBMAX * NN * 256];
__device__ __half g_hidh[BBMAX * NN * 256];  // layer0 output, split
__device__ __half g_hidl[BBMAX * NN * 256];
__device__ __half g_w0 [256 * 256];
__device__ __half g_w1 [128 * 256];

// ---------------- edge preprocessing ----------------------------------

// fused: all blocks zero counts; block 0 lane 0 also detects int64 vs int32
__global__ void zerodetect_kernel(const unsigned int* __restrict__ w, int n) {
    int i = blockIdx.x * blockDim.x + threadIdx.x;
    if (i < n) g_count[i] = 0;
    if (blockIdx.x == 0 && threadIdx.x == 0) {
        int ok = 1;
        for (int k = 1; k < 256; k += 2) {
            if (w[k] != 0u) { ok = 0; break; }
        }
        g_is64 = ok;
    }
}

// one-pass padded-CSR build (incl. self loops)
__global__ void convert_scatter_kernel(const void* __restrict__ edges, int E, int Nn) {
    int i = blockIdx.x * blockDim.x + threadIdx.x;
    int E2 = E + Nn;
    if (i >= E2) return;
    int s, d;
    if (i < E) {
        if (g_is64) {
            const long long* p = (const long long*)edges;
            s = (int)p[i];
            d = (int)p[E + i];
        } else {
            const int* p = (const int*)edges;
            s = p[i];
            d = p[E + i];
        }
    } else {
        s = d = i - E;
    }
    int pos = atomicAdd(&g_count[d], 1);
    g_esrc[d * DEGCAP + pos] = s;
}

// ---------------- fused splits / quantize (x hi/lo, W0, W1) ------------
__global__ void split3_kernel(const float* __restrict__ s0, __half* h0p, __half* l0p, int n0,
                              const float* __restrict__ s1, __half* h1p, int n1,
                              const float* __restrict__ s2, __half* h2p, int n2) {
    int i = blockIdx.x * blockDim.x + threadIdx.x;
    if (i < n0) {
        float4 v = ((const float4*)s0)[i];
        float f[4] = {v.x, v.y, v.z, v.w};
        __half h[4], l[4];
#pragma unroll
        for (int q = 0; q < 4; q++) {
            h[q] = __float2half(f[q]);
            l[q] = __float2half(f[q] - __half2float(h[q]));
        }
        ((uint2*)h0p)[i] = *(uint2*)h;
        ((uint2*)l0p)[i] = *(uint2*)l;
        return;
    }
    i -= n0;
    const float* src; __half* ph;
    if (i < n1)              { src = s1; ph = h1p; }
    else if ((i -= n1) < n2) { src = s2; ph = h2p; }
    else return;
    float4 v = ((const float4*)src)[i];
    __half h[4] = {__float2half(v.x), __float2half(v.y),
                   __float2half(v.z), __float2half(v.w)};
    ((uint2*)ph)[i] = *(uint2*)h;
}

// ---------------- fp16 two-term tensor-core GEMM -----------------------
// C[M][N] = A[M][K] * W[N][K]^T; A pre-split fp16 hi/lo, W single fp16;
// acc += hi*W; acc += lo*W (fp32 accum). Epilogue writes fp32 C + fp16 Cx.

#define MMA16(c, a, b)                                                        \
    asm volatile(                                                             \
        "mma.sync.aligned.m16n8k16.row.col.f32.f16.f16.f32 "                  \
        "{%0,%1,%2,%3},{%4,%5,%6,%7},{%8,%9},{%0,%1,%2,%3};"                  \
        : "+f"((c)[0]), "+f"((c)[1]), "+f"((c)[2]), "+f"((c)[3])              \
        : "r"((a)[0]), "r"((a)[1]), "r"((a)[2]), "r"((a)[3]),                 \
          "r"((b)[0]), "r"((b)[1]))

#define LDSM4(R, addr)                                                        \
    asm volatile(                                                             \
        "ldmatrix.sync.aligned.m8n8.x4.shared.b16 {%0,%1,%2,%3}, [%4];"       \
        : "=r"((R)[0]), "=r"((R)[1]), "=r"((R)[2]), "=r"((R)[3])              \
        : "r"(addr))

#define CPA16(dst, src, sz)                                                   \
    asm volatile("cp.async.cg.shared.global [%0], [%1], 16, %2;"              \
                 :: "r"(dst), "l"(src), "r"(sz) : "memory")
#define CPA_COMMIT() asm volatile("cp.async.commit_group;" ::: "memory")
#define CPA_WAIT1()  asm volatile("cp.async.wait_group 1;" ::: "memory")
#define CPA_WAIT0()  asm volatile("cp.async.wait_group 0;" ::: "memory")

#define GEMM_AP    24                     // padded row (fp16): LDSM conflict-free
#define GEMM_ARRB  (128 * GEMM_AP * 2)    // bytes per array image (6144)
#define GEMM_BUFB  (3 * GEMM_ARRB)        // bytes per stage (Ah, Al, B)
#define GEMM_SMEM  (3 * GEMM_BUFB)        // 3-stage ring = 55296 B

__global__ __launch_bounds__(256, 2)
void gemm_fp16_kernel(const __half* __restrict__ Ah,
                      const __half* __restrict__ Al,
                      const __half* __restrict__ Bw,
                      float* __restrict__ C, __half* __restrict__ Cx,
                      int M, int N, int K) {
    constexpr int BK = 16;
    constexpr int AP = GEMM_AP;
    extern __shared__ __half sm[];

    int tid  = threadIdx.x;
    int wid  = tid >> 5;
    int lane = tid & 31;
    int wm0  = (wid >> 1) * 32;         // 4x2 warp grid, warp tile 32x64
    int wn0  = (wid & 1) * 64;
    int g    = lane >> 2;
    int tg   = lane & 3;
    int m0   = blockIdx.y * 128;
    int n0   = blockIdx.x * 128;

    float acc[2][8][4];
#pragma unroll
    for (int mt = 0; mt < 2; mt++)
#pragma unroll
        for (int nt = 0; nt < 8; nt++)
#pragma unroll
            for (int j = 0; j < 4; j++) acc[mt][nt][j] = 0.f;

    // ldmatrix per-lane offsets (fp16 elements within a tile image)
    int a_off = (wm0 + (lane & 15)) * AP + ((lane >> 4) << 3);
    int bq = lane >> 3, br = lane & 7;
    int b_off = (wn0 + ((bq >> 1) << 3) + br) * AP + ((bq & 1) << 3);

    // cp.async staging: 1 item (16B) per thread per array
    int r0 = tid >> 1, s0g = tid & 1;
    unsigned sz0a = (m0 + r0 < M) ? 16u : 0u;
    size_t ar0 = (size_t)min(m0 + r0, M - 1) * K + s0g * 8;
    size_t br0 = (size_t)(n0 + r0) * K + s0g * 8;
    unsigned d0 = (unsigned)(r0 * 48 + s0g * 16);

    unsigned smb = (unsigned)__cvta_generic_to_shared(sm);

    auto stage = [&](int buf, int koff) {
        unsigned b = smb + buf * GEMM_BUFB;
        CPA16(b + 0 * GEMM_ARRB + d0, Ah + ar0 + koff, sz0a);
        CPA16(b + 1 * GEMM_ARRB + d0, Al + ar0 + koff, sz0a);
        CPA16(b + 2 * GEMM_ARRB + d0, Bw + br0 + koff, 16u);
        CPA_COMMIT();
    };

    int nk = K / BK;
    stage(0, 0);
    stage(1, BK);

    for (int t = 0; t < nk; ++t) {
        CPA_WAIT1();                    // stage t complete
        __syncthreads();                // all warps done with buf (t-1)%3
        if (t + 2 < nk) stage((t + 2) % 3, (t + 2) * BK);

        unsigned abase = smb + (t % 3) * GEMM_BUFB;
        unsigned ah[2][4], alr[2][4];
#pragma unroll
        for (int mt = 0; mt < 2; mt++) {
            LDSM4(ah[mt],  abase + 0 * GEMM_ARRB + (a_off + mt * 16 * AP) * 2);
            LDSM4(alr[mt], abase + 1 * GEMM_ARRB + (a_off + mt * 16 * AP) * 2);
        }
#pragma unroll
        for (int half = 0; half < 2; half++) {
            unsigned bf[2][4];
#pragma unroll
            for (int p = 0; p < 2; p++) {
                unsigned boff = (b_off + (half * 32 + p * 16) * AP) * 2;
                LDSM4(bf[p], abase + 2 * GEMM_ARRB + boff);
            }
#pragma unroll
            for (int mt = 0; mt < 2; mt++)
#pragma unroll
                for (int ntl = 0; ntl < 4; ntl++) {
                    int nt = half * 4 + ntl;
                    MMA16(acc[mt][nt], ah[mt],  &bf[ntl >> 1][(ntl & 1) * 2]);
                    MMA16(acc[mt][nt], alr[mt], &bf[ntl >> 1][(ntl & 1) * 2]);
                }
        }
    }
    CPA_WAIT0();

    // epilogue: fp32 C (for al) + fp16 Cx (for agg gather)
#pragma unroll
    for (int mt = 0; mt < 2; mt++) {
        int r = m0 + wm0 + mt * 16 + g;
#pragma unroll
        for (int nt = 0; nt < 8; nt++) {
            int col = n0 + wn0 + nt * 8 + 2 * tg;
            if (r < M) {
                *(float2*)(C + (size_t)r * N + col) =
                    make_float2(acc[mt][nt][0], acc[mt][nt][1]);
                *(__half2*)(Cx + (size_t)r * N + col) =
                    __floats2half2_rn(acc[mt][nt][0], acc[mt][nt][1]);
            }
            if (r + 8 < M) {
                *(float2*)(C + (size_t)(r + 8) * N + col) =
                    make_float2(acc[mt][nt][2], acc[mt][nt][3]);
                *(__half2*)(Cx + (size_t)(r + 8) * N + col) =
                    __floats2half2_rn(acc[mt][nt][2], acc[mt][nt][3]);
            }
        }
    }
}

// ---------------- attention-logit dot products (fp32 h) ----------------
template <int F>
__global__ void al_kernel(const float* __restrict__ h, const float* __restrict__ asrc,
                          const float* __restrict__ adst, float* __restrict__ als,
                          float* __restrict__ ald, int M) {
    int warp = (blockIdx.x * blockDim.x + threadIdx.x) >> 5;
    int lane = threadIdx.x & 31;
    if (warp >= M) return;
    const float* row = h + (size_t)warp * F;
    float s = 0.f, d = 0.f;
#pragma unroll
    for (int i = lane; i < F; i += 32) {
        float v = row[i];
        s += v * asrc[i];
        d += v * adst[i];
    }
#pragma unroll
    for (int o = 16; o; o >>= 1) {
        s += __shfl_xor_sync(0xffffffffu, s, o);
        d += __shfl_xor_sync(0xffffffffu, d, o);
    }
    if (!lane) {
        als[warp] = s;
        ald[warp] = d;
    }
}

// ---------------- softmax aggregation (one block per (batch,dst)) ------
// R9 skeleton (4 edge groups, float4 accum, single-STS128 reduce),
// but gathering from the fp16 h copy: uint2 (4 halves) per thread.
template <int F, bool SPLIT>
__global__ __launch_bounds__(F)
void agg_kernel(const __half* __restrict__ hx, const float* __restrict__ als,
                const float* __restrict__ ald, const float* __restrict__ bias,
                float* __restrict__ out,
                __half* __restrict__ outh, __half* __restrict__ outl,
                int Nn) {
    constexpr int NW = F / 32;
    constexpr int FQ = F / 4;
    __shared__ float sred[NW];
    __shared__ float sbc;
    __shared__ float sw[DEGCAP + 4];
    __shared__ int   ssrc[DEGCAP + 4];
    __shared__ float4 sred4[4][FQ];

    int bx   = blockIdx.x;
    int v    = bx % Nn;
    int b    = bx / Nn;
    int tid  = threadIdx.x;
    int lane = tid & 31;
    int w    = tid >> 5;
    int begin = v * DEGCAP;
    int deg   = g_count[v];
    int base  = b * Nn;
    float aldv = ald[base + v];

    // pass 1a: segment max
    float lm = -1e30f;
    for (int j = tid; j < deg; j += F) {
        float e = als[base + g_esrc[begin + j]] + aldv;
        e = (e < 0.f) ? 0.2f * e : e;
        lm = fmaxf(lm, e);
    }
#pragma unroll
    for (int o = 16; o; o >>= 1) lm = fmaxf(lm, __shfl_xor_sync(0xffffffffu, lm, o));
    if (!lane) sred[w] = lm;
    __syncthreads();
    if (w == 0) {
        float x = (lane < NW) ? sred[lane] : -1e30f;
#pragma unroll
        for (int o = 16; o; o >>= 1) x = fmaxf(x, __shfl_xor_sync(0xffffffffu, x, o));
        if (!lane) sbc = x;
    }
    __syncthreads();
    float m = sbc;

    // pass 1b: denominator + stash per-edge exp weights in shared
    float ls = 0.f;
    for (int j = tid; j < deg; j += F) {
        int s = g_esrc[begin + j];
        float e = als[base + s] + aldv;
        e = (e < 0.f) ? 0.2f * e : e;
        float ex = __expf(e - m);
        ssrc[j] = s;
        sw[j]   = ex;
        ls += ex;
    }
    if (tid < 4) {                      // zero-pad to multiple of 4
        int j = deg + tid;
        sw[j] = 0.f;
        ssrc[j] = 0;
    }
#pragma unroll
    for (int o = 16; o; o >>= 1) ls += __shfl_xor_sync(0xffffffffu, ls, o);
    if (!lane) sred[w] = ls;
    __syncthreads();
    if (w == 0) {
        float x = (lane < NW) ? sred[lane] : 0.f;
#pragma unroll
        for (int o = 16; o; o >>= 1) x += __shfl_xor_sync(0xffffffffu, x, o);
        if (!lane) sbc = x;
    }
    __syncthreads();
    float inv = 1.f / (sbc + 1e-16f);

    // pass 2: fp16 gather — edge group eg, feature quad fq (uint2 = 4 halves)
    int eg = tid / FQ;
    int fq = tid % FQ;
    float4 a4 = make_float4(0.f, 0.f, 0.f, 0.f);
#pragma unroll 2
    for (int j0 = 0; j0 < deg; j0 += 4) {
        int j = j0 + eg;                // always staged (zero-padded)
        float wj = sw[j];
        uint2 hv = *(const uint2*)(hx + (size_t)(base + ssrc[j]) * F + fq * 4);
        float2 f0 = __half22float2(*(const __half2*)&hv.x);
        float2 f1 = __half22float2(*(const __half2*)&hv.y);
        a4.x += wj * f0.x;
        a4.y += wj * f0.y;
        a4.z += wj * f1.x;
        a4.w += wj * f1.y;
    }
    sred4[eg][fq] = a4;
    __syncthreads();

    int q = tid >> 2, c = tid & 3;
    float r = ((const float*)&sred4[0][q])[c] + ((const float*)&sred4[1][q])[c] +
              ((const float*)&sred4[2][q])[c] + ((const float*)&sred4[3][q])[c];
    r = r * inv + bias[tid];
    r = r > 0.f ? r : 0.f;
    size_t oi = (size_t)(base + v) * F + tid;
    if (SPLIT) {
        __half hi = __float2half(r);
        __half lo = __float2half(r - __half2float(hi));
        outh[oi] = hi;
        outl[oi] = lo;
    } else {
        out[oi] = r;
    }
}

// ---------------- launch ----------------------------------------------
extern "C" void kernel_launch(void* const* d_in, const int* in_sizes, int n_in,
                              void* d_out, int out_size) {
    const float* x     = (const float*)d_in[0];
    const void*  edges = d_in[1];
    const float* W0    = (const float*)d_in[2];
    const float* b0    = (const float*)d_in[3];
    const float* asrc0 = (const float*)d_in[4];
    const float* adst0 = (const float*)d_in[5];
    const float* W1    = (const float*)d_in[6];
    const float* b1    = (const float*)d_in[7];
    const float* asrc1 = (const float*)d_in[8];
    const float* adst1 = (const float*)d_in[9];
    float* out = (float*)d_out;

    int F1 = in_sizes[3];            // 256
    int F0 = in_sizes[2] / F1;       // 256
    int F2 = in_sizes[7];            // 128
    int E  = in_sizes[1] / 2;        // 320000
    int M  = in_sizes[0] / F0;       // B*N = 40000
    int Nn = NN;                     // 10000
    int E2 = E + Nn;

    float *p_h0, *p_h1, *p_als, *p_ald;
    __half *p_h0x, *p_h1x, *p_xh, *p_xl, *p_hidh, *p_hidl, *p_w0, *p_w1;
    cudaGetSymbolAddress((void**)&p_h0,   g_h0);
    cudaGetSymbolAddress((void**)&p_h1,   g_h1);
    cudaGetSymbolAddress((void**)&p_h0x,  g_h0x);
    cudaGetSymbolAddress((void**)&p_h1x,  g_h1x);
    cudaGetSymbolAddress((void**)&p_als,  g_als);
    cudaGetSymbolAddress((void**)&p_ald,  g_ald);
    cudaGetSymbolAddress((void**)&p_xh,   g_xh);
    cudaGetSymbolAddress((void**)&p_xl,   g_xl);
    cudaGetSymbolAddress((void**)&p_hidh, g_hidh);
    cudaGetSymbolAddress((void**)&p_hidl, g_hidl);
    cudaGetSymbolAddress((void**)&p_w0,   g_w0);
    cudaGetSymbolAddress((void**)&p_w1,   g_w1);

    cudaFuncSetAttribute(gemm_fp16_kernel,
                         cudaFuncAttributeMaxDynamicSharedMemorySize, GEMM_SMEM);

    int mtiles = (M + 127) / 128;
    int n0q = M * F0 / 4, n1q = F1 * F0 / 4, n2q = F2 * F1 / 4;

    // (0) fused splits, (1) zero+detect, (2) CSR build, (3) GEMM0 [profiled]
    split3_kernel<<<(n0q + n1q + n2q + 255) / 256, 256>>>(
        x, p_xh, p_xl, n0q, W0, p_w0, n1q, W1, p_w1, n2q);
    zerodetect_kernel<<<(Nn + 255) / 256, 256>>>((const unsigned int*)edges, Nn);
    convert_scatter_kernel<<<(E2 + 255) / 256, 256>>>(edges, E, Nn);

    gemm_fp16_kernel<<<dim3(F1 / 128, mtiles), 256, GEMM_SMEM>>>(
        p_xh, p_xl, p_w0, p_h0, p_h0x, M, F1, F0);
    al_kernel<256><<<(M * 32 + 255) / 256, 256>>>(p_h0, asrc0, adst0, p_als, p_ald, M);
    agg_kernel<256, true><<<M, 256>>>(p_h0x, p_als, p_ald, b0,
                                      nullptr, p_hidh, p_hidl, Nn);

    gemm_fp16_kernel<<<dim3(F2 / 128, mtiles), 256, GEMM_SMEM>>>(
        p_hidh, p_hidl, p_w1, p_h1, p_h1x, M, F2, F1);
    al_kernel<128><<<(M * 32 + 255) / 256, 256>>>(p_h1, asrc1, adst1, p_als, p_ald, M);
    agg_kernel<128, false><<<M, 128>>>(p_h1x, p_als, p_ald, b1,
                                       out, nullptr, nullptr, Nn);
}

// round 12
// speedup vs baseline: 1.2522x; 1.0215x over previous
#include <cuda_runtime.h>
#include <cuda_fp16.h>
#include <cstdint>

// ---------------- problem constants (registry shapes) ----------------
#define NN      10000          // nodes per graph
#define EMAXE   320000         // edges (without self loops)
#define E2MAX   (EMAXE + NN)   // + self loops
#define BBMAX   4              // batch
#define DEGCAP  128            // padded-CSR capacity (max degree ~60 => 12 sigma safe)

// ---------------- device scratch (no allocations allowed) -------------
__device__ int   g_esrc[NN * DEGCAP];   // padded CSR: src per slot
__device__ int   g_count[NN];
__device__ int   g_is64;
__device__ float g_h0 [BBMAX * NN * 256];   // layer0 pre-attention features (fp32)
__device__ float g_h1 [BBMAX * NN * 128];   // layer1 pre-attention features (fp32)
__device__ float g_als[BBMAX * NN];
__device__ float g_ald[BBMAX * NN];
// fp16 operands: x split hi/lo (exact to ~2^-22), W single fp16 (err 2^-12)
__device__ __half g_xh [BBMAX * NN * 256];
__device__ __half g_xl [BBMAX * NN * 256];
__device__ __half g_hidh[BBMAX * NN * 256];  // layer0 output, split
__device__ __half g_hidl[BBMAX * NN * 256];
__device__ __half g_w0 [256 * 256];
__device__ __half g_w1 [128 * 256];

// ---------------- edge preprocessing ----------------------------------

// fused: all blocks zero counts; block 0 lane 0 also detects int64 vs int32
__global__ void zerodetect_kernel(const unsigned int* __restrict__ w, int n) {
    int i = blockIdx.x * blockDim.x + threadIdx.x;
    if (i < n) g_count[i] = 0;
    if (blockIdx.x == 0 && threadIdx.x == 0) {
        int ok = 1;
        for (int k = 1; k < 256; k += 2) {
            if (w[k] != 0u) { ok = 0; break; }
        }
        g_is64 = ok;
    }
}

// one-pass padded-CSR build (incl. self loops)
__global__ void convert_scatter_kernel(const void* __restrict__ edges, int E, int Nn) {
    int i = blockIdx.x * blockDim.x + threadIdx.x;
    int E2 = E + Nn;
    if (i >= E2) return;
    int s, d;
    if (i < E) {
        if (g_is64) {
            const long long* p = (const long long*)edges;
            s = (int)p[i];
            d = (int)p[E + i];
        } else {
            const int* p = (const int*)edges;
            s = p[i];
            d = p[E + i];
        }
    } else {
        s = d = i - E;
    }
    int pos = atomicAdd(&g_count[d], 1);
    g_esrc[d * DEGCAP + pos] = s;
}

// ---------------- fused splits / quantize (x hi/lo, W0, W1) ------------
__global__ void split3_kernel(const float* __restrict__ s0, __half* h0p, __half* l0p, int n0,
                              const float* __restrict__ s1, __half* h1p, int n1,
                              const float* __restrict__ s2, __half* h2p, int n2) {
    int i = blockIdx.x * blockDim.x + threadIdx.x;
    if (i < n0) {
        float4 v = ((const float4*)s0)[i];
        float f[4] = {v.x, v.y, v.z, v.w};
        __half h[4], l[4];
#pragma unroll
        for (int q = 0; q < 4; q++) {
            h[q] = __float2half(f[q]);
            l[q] = __float2half(f[q] - __half2float(h[q]));
        }
        ((uint2*)h0p)[i] = *(uint2*)h;
        ((uint2*)l0p)[i] = *(uint2*)l;
        return;
    }
    i -= n0;
    const float* src; __half* ph;
    if (i < n1)              { src = s1; ph = h1p; }
    else if ((i -= n1) < n2) { src = s2; ph = h2p; }
    else return;
    float4 v = ((const float4*)src)[i];
    __half h[4] = {__float2half(v.x), __float2half(v.y),
                   __float2half(v.z), __float2half(v.w)};
    ((uint2*)ph)[i] = *(uint2*)h;
}

// ---------------- fp16 two-term tensor-core GEMM -----------------------
// C[M][N] = A[M][K] * W[N][K]^T; A pre-split fp16 hi/lo, W single fp16;
// acc += hi*W; acc += lo*W (fp32 accum).

#define MMA16(c, a, b)                                                        \
    asm volatile(                                                             \
        "mma.sync.aligned.m16n8k16.row.col.f32.f16.f16.f32 "                  \
        "{%0,%1,%2,%3},{%4,%5,%6,%7},{%8,%9},{%0,%1,%2,%3};"                  \
        : "+f"((c)[0]), "+f"((c)[1]), "+f"((c)[2]), "+f"((c)[3])              \
        : "r"((a)[0]), "r"((a)[1]), "r"((a)[2]), "r"((a)[3]),                 \
          "r"((b)[0]), "r"((b)[1]))

#define LDSM4(R, addr)                                                        \
    asm volatile(                                                             \
        "ldmatrix.sync.aligned.m8n8.x4.shared.b16 {%0,%1,%2,%3}, [%4];"       \
        : "=r"((R)[0]), "=r"((R)[1]), "=r"((R)[2]), "=r"((R)[3])              \
        : "r"(addr))

#define CPA16(dst, src, sz)                                                   \
    asm volatile("cp.async.cg.shared.global [%0], [%1], 16, %2;"              \
                 :: "r"(dst), "l"(src), "r"(sz) : "memory")
#define CPA_COMMIT() asm volatile("cp.async.commit_group;" ::: "memory")
#define CPA_WAIT1()  asm volatile("cp.async.wait_group 1;" ::: "memory")
#define CPA_WAIT0()  asm volatile("cp.async.wait_group 0;" ::: "memory")

#define GEMM_AP    24                     // padded row (fp16): LDSM conflict-free
#define GEMM_ARRB  (128 * GEMM_AP * 2)    // bytes per array image (6144)
#define GEMM_BUFB  (3 * GEMM_ARRB)        // bytes per stage (Ah, Al, B)
#define GEMM_SMEM  (3 * GEMM_BUFB)        // 3-stage ring = 55296 B

__global__ __launch_bounds__(256, 2)
void gemm_fp16_kernel(const __half* __restrict__ Ah,
                      const __half* __restrict__ Al,
                      const __half* __restrict__ Bw,
                      float* __restrict__ C, int M, int N, int K) {
    constexpr int BK = 16;
    constexpr int AP = GEMM_AP;
    extern __shared__ __half sm[];

    int tid  = threadIdx.x;
    int wid  = tid >> 5;
    int lane = tid & 31;
    int wm0  = (wid >> 1) * 32;         // 4x2 warp grid, warp tile 32x64
    int wn0  = (wid & 1) * 64;
    int g    = lane >> 2;
    int tg   = lane & 3;
    int m0   = blockIdx.y * 128;
    int n0   = blockIdx.x * 128;

    float acc[2][8][4];
#pragma unroll
    for (int mt = 0; mt < 2; mt++)
#pragma unroll
        for (int nt = 0; nt < 8; nt++)
#pragma unroll
            for (int j = 0; j < 4; j++) acc[mt][nt][j] = 0.f;

    int a_off = (wm0 + (lane & 15)) * AP + ((lane >> 4) << 3);
    int bq = lane >> 3, br = lane & 7;
    int b_off = (wn0 + ((bq >> 1) << 3) + br) * AP + ((bq & 1) << 3);

    int r0 = tid >> 1, s0g = tid & 1;
    unsigned sz0a = (m0 + r0 < M) ? 16u : 0u;
    size_t ar0 = (size_t)min(m0 + r0, M - 1) * K + s0g * 8;
    size_t br0 = (size_t)(n0 + r0) * K + s0g * 8;
    unsigned d0 = (unsigned)(r0 * 48 + s0g * 16);

    unsigned smb = (unsigned)__cvta_generic_to_shared(sm);

    auto stage = [&](int buf, int koff) {
        unsigned b = smb + buf * GEMM_BUFB;
        CPA16(b + 0 * GEMM_ARRB + d0, Ah + ar0 + koff, sz0a);
        CPA16(b + 1 * GEMM_ARRB + d0, Al + ar0 + koff, sz0a);
        CPA16(b + 2 * GEMM_ARRB + d0, Bw + br0 + koff, 16u);
        CPA_COMMIT();
    };

    int nk = K / BK;
    stage(0, 0);
    stage(1, BK);

    for (int t = 0; t < nk; ++t) {
        CPA_WAIT1();
        __syncthreads();
        if (t + 2 < nk) stage((t + 2) % 3, (t + 2) * BK);

        unsigned abase = smb + (t % 3) * GEMM_BUFB;
        unsigned ah[2][4], alr[2][4];
#pragma unroll
        for (int mt = 0; mt < 2; mt++) {
            LDSM4(ah[mt],  abase + 0 * GEMM_ARRB + (a_off + mt * 16 * AP) * 2);
            LDSM4(alr[mt], abase + 1 * GEMM_ARRB + (a_off + mt * 16 * AP) * 2);
        }
#pragma unroll
        for (int half = 0; half < 2; half++) {
            unsigned bf[2][4];
#pragma unroll
            for (int p = 0; p < 2; p++) {
                unsigned boff = (b_off + (half * 32 + p * 16) * AP) * 2;
                LDSM4(bf[p], abase + 2 * GEMM_ARRB + boff);
            }
#pragma unroll
            for (int mt = 0; mt < 2; mt++)
#pragma unroll
                for (int ntl = 0; ntl < 4; ntl++) {
                    int nt = half * 4 + ntl;
                    MMA16(acc[mt][nt], ah[mt],  &bf[ntl >> 1][(ntl & 1) * 2]);
                    MMA16(acc[mt][nt], alr[mt], &bf[ntl >> 1][(ntl & 1) * 2]);
                }
        }
    }
    CPA_WAIT0();

#pragma unroll
    for (int mt = 0; mt < 2; mt++) {
        int r = m0 + wm0 + mt * 16 + g;
#pragma unroll
        for (int nt = 0; nt < 8; nt++) {
            int col = n0 + wn0 + nt * 8 + 2 * tg;
            if (r < M)
                *(float2*)(C + (size_t)r * N + col) =
                    make_float2(acc[mt][nt][0], acc[mt][nt][1]);
            if (r + 8 < M)
                *(float2*)(C + (size_t)(r + 8) * N + col) =
                    make_float2(acc[mt][nt][2], acc[mt][nt][3]);
        }
    }
}

// ---------------- attention-logit dot products (fp32 h) ----------------
template <int F>
__global__ void al_kernel(const float* __restrict__ h, const float* __restrict__ asrc,
                          const float* __restrict__ adst, float* __restrict__ als,
                          float* __restrict__ ald, int M) {
    int warp = (blockIdx.x * blockDim.x + threadIdx.x) >> 5;
    int lane = threadIdx.x & 31;
    if (warp >= M) return;
    const float* row = h + (size_t)warp * F;
    float s = 0.f, d = 0.f;
#pragma unroll
    for (int i = lane; i < F; i += 32) {
        float v = row[i];
        s += v * asrc[i];
        d += v * adst[i];
    }
#pragma unroll
    for (int o = 16; o; o >>= 1) {
        s += __shfl_xor_sync(0xffffffffu, s, o);
        d += __shfl_xor_sync(0xffffffffu, d, o);
    }
    if (!lane) {
        als[warp] = s;
        ald[warp] = d;
    }
}

// ---------------- softmax aggregation: one block per node, ALL 4 batches
// Stages esrc once; one scattered-logit pass, one combined max reduce, one
// combined sum reduce; single gather loop with 4 interleaved batch
// accumulators (MLP ~16); single-STS128 cross-group reduce per batch.
template <int F, bool SPLIT>
__global__ __launch_bounds__(F)
void agg4_kernel(const float* __restrict__ h, const float* __restrict__ als,
                 const float* __restrict__ ald, const float* __restrict__ bias,
                 float* __restrict__ out,
                 __half* __restrict__ outh, __half* __restrict__ outl,
                 int Nn) {
    constexpr int NW = F / 32;
    constexpr int FQ = F / 4;
    __shared__ float  se[BBMAX][DEGCAP + 4];   // logits -> exp weights (in place)
    __shared__ int    ssrc[DEGCAP + 4];
    __shared__ float  sredm[BBMAX][NW];
    __shared__ float  sbc[BBMAX];
    __shared__ float4 sred4[BBMAX][4][FQ];

    int v    = blockIdx.x;
    int tid  = threadIdx.x;
    int lane = tid & 31;
    int w    = tid >> 5;
    int begin = v * DEGCAP;
    int deg   = g_count[v];

    float aldv[BBMAX];
#pragma unroll
    for (int b = 0; b < BBMAX; b++) aldv[b] = ald[b * Nn + v];

    // stage srcs + logits for all batches; track per-thread max
    float lm[BBMAX];
#pragma unroll
    for (int b = 0; b < BBMAX; b++) lm[b] = -1e30f;
    for (int j = tid; j < deg; j += F) {
        int s = g_esrc[begin + j];
        ssrc[j] = s;
#pragma unroll
        for (int b = 0; b < BBMAX; b++) {
            float e = als[b * Nn + s] + aldv[b];
            e = (e < 0.f) ? 0.2f * e : e;
            se[b][j] = e;
            lm[b] = fmaxf(lm[b], e);
        }
    }
    if (tid < 4) {                      // pad to multiple of 4 edge groups
        int j = deg + tid;
        ssrc[j] = 0;
#pragma unroll
        for (int b = 0; b < BBMAX; b++) se[b][j] = -1e30f;
    }

    // combined block max reduce (4 batches at once)
#pragma unroll
    for (int b = 0; b < BBMAX; b++)
#pragma unroll
        for (int o = 16; o; o >>= 1)
            lm[b] = fmaxf(lm[b], __shfl_xor_sync(0xffffffffu, lm[b], o));
    if (!lane)
#pragma unroll
        for (int b = 0; b < BBMAX; b++) sredm[b][w] = lm[b];
    __syncthreads();
    if (w == 0) {
#pragma unroll
        for (int b = 0; b < BBMAX; b++) {
            float x = (lane < NW) ? sredm[b][lane] : -1e30f;
#pragma unroll
            for (int o = 16; o; o >>= 1)
                x = fmaxf(x, __shfl_xor_sync(0xffffffffu, x, o));
            if (!lane) sbc[b] = x;
        }
    }
    __syncthreads();
    float mb[BBMAX];
#pragma unroll
    for (int b = 0; b < BBMAX; b++) mb[b] = sbc[b];
    __syncthreads();                    // sbc reused below

    // exp in place + combined sum reduce
    float ls[BBMAX];
#pragma unroll
    for (int b = 0; b < BBMAX; b++) ls[b] = 0.f;
    for (int j = tid; j < deg; j += F) {
#pragma unroll
        for (int b = 0; b < BBMAX; b++) {
            float ex = __expf(se[b][j] - mb[b]);
            se[b][j] = ex;
            ls[b] += ex;
        }
    }
    if (tid < 4) {                      // pad weights = 0
        int j = deg + tid;
#pragma unroll
        for (int b = 0; b < BBMAX; b++) se[b][j] = 0.f;
    }
#pragma unroll
    for (int b = 0; b < BBMAX; b++)
#pragma unroll
        for (int o = 16; o; o >>= 1)
            ls[b] += __shfl_xor_sync(0xffffffffu, ls[b], o);
    if (!lane)
#pragma unroll
        for (int b = 0; b < BBMAX; b++) sredm[b][w] = ls[b];
    __syncthreads();
    if (w == 0) {
#pragma unroll
        for (int b = 0; b < BBMAX; b++) {
            float x = (lane < NW) ? sredm[b][lane] : 0.f;
#pragma unroll
            for (int o = 16; o; o >>= 1)
                x += __shfl_xor_sync(0xffffffffu, x, o);
            if (!lane) sbc[b] = x;
        }
    }
    __syncthreads();
    float inv[BBMAX];
#pragma unroll
    for (int b = 0; b < BBMAX; b++) inv[b] = 1.f / (sbc[b] + 1e-16f);

    // gather: edge group eg, feature quad fq; 4 batches interleaved (MLP ~16)
    int eg = tid / FQ;
    int fq = tid % FQ;
    float4 a[BBMAX];
#pragma unroll
    for (int b = 0; b < BBMAX; b++) a[b] = make_float4(0.f, 0.f, 0.f, 0.f);
    for (int j0 = 0; j0 < deg; j0 += 4) {
        int j = j0 + eg;
        int s = ssrc[j];
#pragma unroll
        for (int b = 0; b < BBMAX; b++) {
            float wj = se[b][j];
            float4 hv = *(const float4*)(h + (size_t)(b * Nn + s) * F + fq * 4);
            a[b].x += wj * hv.x;
            a[b].y += wj * hv.y;
            a[b].z += wj * hv.z;
            a[b].w += wj * hv.w;
        }
    }
#pragma unroll
    for (int b = 0; b < BBMAX; b++) sred4[b][eg][fq] = a[b];
    __syncthreads();

    int q = tid >> 2, c = tid & 3;
#pragma unroll
    for (int b = 0; b < BBMAX; b++) {
        float r = ((const float*)&sred4[b][0][q])[c] + ((const float*)&sred4[b][1][q])[c] +
                  ((const float*)&sred4[b][2][q])[c] + ((const float*)&sred4[b][3][q])[c];
        r = r * inv[b] + bias[tid];
        r = r > 0.f ? r : 0.f;
        size_t oi = (size_t)(b * Nn + v) * F + tid;
        if (SPLIT) {
            __half hi = __float2half(r);
            __half lo = __float2half(r - __half2float(hi));
            outh[oi] = hi;
            outl[oi] = lo;
        } else {
            out[oi] = r;
        }
    }
}

// ---------------- launch ----------------------------------------------
extern "C" void kernel_launch(void* const* d_in, const int* in_sizes, int n_in,
                              void* d_out, int out_size) {
    const float* x     = (const float*)d_in[0];
    const void*  edges = d_in[1];
    const float* W0    = (const float*)d_in[2];
    const float* b0    = (const float*)d_in[3];
    const float* asrc0 = (const float*)d_in[4];
    const float* adst0 = (const float*)d_in[5];
    const float* W1    = (const float*)d_in[6];
    const float* b1    = (const float*)d_in[7];
    const float* asrc1 = (const float*)d_in[8];
    const float* adst1 = (const float*)d_in[9];
    float* out = (float*)d_out;

    int F1 = in_sizes[3];            // 256
    int F0 = in_sizes[2] / F1;       // 256
    int F2 = in_sizes[7];            // 128
    int E  = in_sizes[1] / 2;        // 320000
    int M  = in_sizes[0] / F0;       // B*N = 40000
    int Nn = NN;                     // 10000
    int E2 = E + Nn;

    float *p_h0, *p_h1, *p_als, *p_ald;
    __half *p_xh, *p_xl, *p_hidh, *p_hidl, *p_w0, *p_w1;
    cudaGetSymbolAddress((void**)&p_h0,   g_h0);
    cudaGetSymbolAddress((void**)&p_h1,   g_h1);
    cudaGetSymbolAddress((void**)&p_als,  g_als);
    cudaGetSymbolAddress((void**)&p_ald,  g_ald);
    cudaGetSymbolAddress((void**)&p_xh,   g_xh);
    cudaGetSymbolAddress((void**)&p_xl,   g_xl);
    cudaGetSymbolAddress((void**)&p_hidh, g_hidh);
    cudaGetSymbolAddress((void**)&p_hidl, g_hidl);
    cudaGetSymbolAddress((void**)&p_w0,   g_w0);
    cudaGetSymbolAddress((void**)&p_w1,   g_w1);

    cudaFuncSetAttribute(gemm_fp16_kernel,
                         cudaFuncAttributeMaxDynamicSharedMemorySize, GEMM_SMEM);

    int mtiles = (M + 127) / 128;
    int n0q = M * F0 / 4, n1q = F1 * F0 / 4, n2q = F2 * F1 / 4;

    // (0) fused splits, (1) zero+detect, (2) CSR build, (3) GEMM0 [profiled]
    split3_kernel<<<(n0q + n1q + n2q + 255) / 256, 256>>>(
        x, p_xh, p_xl, n0q, W0, p_w0, n1q, W1, p_w1, n2q);
    zerodetect_kernel<<<(Nn + 255) / 256, 256>>>((const unsigned int*)edges, Nn);
    convert_scatter_kernel<<<(E2 + 255) / 256, 256>>>(edges, E, Nn);

    gemm_fp16_kernel<<<dim3(F1 / 128, mtiles), 256, GEMM_SMEM>>>(
        p_xh, p_xl, p_w0, p_h0, M, F1, F0);
    al_kernel<256><<<(M * 32 + 255) / 256, 256>>>(p_h0, asrc0, adst0, p_als, p_ald, M);
    agg4_kernel<256, true><<<Nn, 256>>>(p_h0, p_als, p_ald, b0,
                                        nullptr, p_hidh, p_hidl, Nn);

    gemm_fp16_kernel<<<dim3(F2 / 128, mtiles), 256, GEMM_SMEM>>>(
        p_hidh, p_hidl, p_w1, p_h1, M, F2, F1);
    al_kernel<128><<<(M * 32 + 255) / 256, 256>>>(p_h1, asrc1, adst1, p_als, p_ald, M);
    agg4_kernel<128, false><<<Nn, 128>>>(p_h1, p_als, p_ald, b1,
                                         out, nullptr, nullptr, Nn);
}

// round 13
// speedup vs baseline: 1.3185x; 1.0530x over previous
#include <cuda_runtime.h>
#include <cuda_fp16.h>
#include <cstdint>

// ---------------- problem constants (registry shapes) ----------------
#define NN      10000          // nodes per graph
#define EMAXE   320000         // edges (without self loops)
#define E2MAX   (EMAXE + NN)   // + self loops
#define BBMAX   4              // batch
#define DEGCAP  128            // padded-CSR capacity (max degree ~60 => 12 sigma safe)

// ---------------- device scratch (no allocations allowed) -------------
__device__ int   g_esrc[NN * DEGCAP];   // padded CSR: src per slot
__device__ int   g_count[NN];
__device__ int   g_is64;
__device__ float g_h0 [BBMAX * NN * 256];   // layer0 pre-attention features (fp32)
__device__ float g_h1 [BBMAX * NN * 128];   // layer1 pre-attention features (fp32)
__device__ float g_als4a[NN * 4];           // batch-transposed attention logits
__device__ float g_ald4a[NN * 4];
__device__ float g_als4b[NN * 4];
__device__ float g_ald4b[NN * 4];
// fp16 operands: x split hi/lo (exact to ~2^-22), W single fp16 (err 2^-12)
__device__ __half g_xh [BBMAX * NN * 256];
__device__ __half g_xl [BBMAX * NN * 256];
__device__ __half g_hidh[BBMAX * NN * 256];  // layer0 output, split
__device__ __half g_hidl[BBMAX * NN * 256];
__device__ __half g_w0 [256 * 256];
__device__ __half g_w1 [128 * 256];

// ---------------- edge preprocessing ----------------------------------

// fused: zero counts + per-layer logit accumulators; lane 0 detects int64
__global__ void zerodetect_kernel(const unsigned int* __restrict__ w, int Nn) {
    int i = blockIdx.x * blockDim.x + threadIdx.x;
    if (i < Nn) g_count[i] = 0;
    if (i < Nn * 4) {
        g_als4a[i] = 0.f;
        g_ald4a[i] = 0.f;
        g_als4b[i] = 0.f;
        g_ald4b[i] = 0.f;
    }
    if (blockIdx.x == 0 && threadIdx.x == 0) {
        int ok = 1;
        for (int k = 1; k < 256; k += 2) {
            if (w[k] != 0u) { ok = 0; break; }
        }
        g_is64 = ok;
    }
}

// one-pass padded-CSR build (incl. self loops)
__global__ void convert_scatter_kernel(const void* __restrict__ edges, int E, int Nn) {
    int i = blockIdx.x * blockDim.x + threadIdx.x;
    int E2 = E + Nn;
    if (i >= E2) return;
    int s, d;
    if (i < E) {
        if (g_is64) {
            const long long* p = (const long long*)edges;
            s = (int)p[i];
            d = (int)p[E + i];
        } else {
            const int* p = (const int*)edges;
            s = p[i];
            d = p[E + i];
        }
    } else {
        s = d = i - E;
    }
    int pos = atomicAdd(&g_count[d], 1);
    g_esrc[d * DEGCAP + pos] = s;
}

// ---------------- fused splits / quantize (x hi/lo, W0, W1) ------------
__global__ void split3_kernel(const float* __restrict__ s0, __half* h0p, __half* l0p, int n0,
                              const float* __restrict__ s1, __half* h1p, int n1,
                              const float* __restrict__ s2, __half* h2p, int n2) {
    int i = blockIdx.x * blockDim.x + threadIdx.x;
    if (i < n0) {
        float4 v = ((const float4*)s0)[i];
        float f[4] = {v.x, v.y, v.z, v.w};
        __half h[4], l[4];
#pragma unroll
        for (int q = 0; q < 4; q++) {
            h[q] = __float2half(f[q]);
            l[q] = __float2half(f[q] - __half2float(h[q]));
        }
        ((uint2*)h0p)[i] = *(uint2*)h;
        ((uint2*)l0p)[i] = *(uint2*)l;
        return;
    }
    i -= n0;
    const float* src; __half* ph;
    if (i < n1)              { src = s1; ph = h1p; }
    else if ((i -= n1) < n2) { src = s2; ph = h2p; }
    else return;
    float4 v = ((const float4*)src)[i];
    __half h[4] = {__float2half(v.x), __float2half(v.y),
                   __float2half(v.z), __float2half(v.w)};
    ((uint2*)ph)[i] = *(uint2*)h;
}

// ---------------- fp16 two-term tensor-core GEMM + fused al ------------
// C[M][N] = A[M][K] * W[N][K]^T; A pre-split fp16 hi/lo, W single fp16;
// acc += hi*W; acc += lo*W (fp32 accum). Epilogue also computes partial
// dot(h_row, asrc/adst) and atomically accumulates into batch-transposed
// als4[v*4+b] / ald4[v*4+b].

#define MMA16(c, a, b)                                                        \
    asm volatile(                                                             \
        "mma.sync.aligned.m16n8k16.row.col.f32.f16.f16.f32 "                  \
        "{%0,%1,%2,%3},{%4,%5,%6,%7},{%8,%9},{%0,%1,%2,%3};"                  \
        : "+f"((c)[0]), "+f"((c)[1]), "+f"((c)[2]), "+f"((c)[3])              \
        : "r"((a)[0]), "r"((a)[1]), "r"((a)[2]), "r"((a)[3]),                 \
          "r"((b)[0]), "r"((b)[1]))

#define LDSM4(R, addr)                                                        \
    asm volatile(                                                             \
        "ldmatrix.sync.aligned.m8n8.x4.shared.b16 {%0,%1,%2,%3}, [%4];"       \
        : "=r"((R)[0]), "=r"((R)[1]), "=r"((R)[2]), "=r"((R)[3])              \
        : "r"(addr))

#define CPA16(dst, src, sz)                                                   \
    asm volatile("cp.async.cg.shared.global [%0], [%1], 16, %2;"              \
                 :: "r"(dst), "l"(src), "r"(sz) : "memory")
#define CPA_COMMIT() asm volatile("cp.async.commit_group;" ::: "memory")
#define CPA_WAIT1()  asm volatile("cp.async.wait_group 1;" ::: "memory")
#define CPA_WAIT0()  asm volatile("cp.async.wait_group 0;" ::: "memory")

#define GEMM_AP    24                     // padded row (fp16): LDSM conflict-free
#define GEMM_ARRB  (128 * GEMM_AP * 2)    // bytes per array image (6144)
#define GEMM_BUFB  (3 * GEMM_ARRB)        // bytes per stage (Ah, Al, B)
#define GEMM_SMEM  (3 * GEMM_BUFB)        // 3-stage ring = 55296 B

__global__ __launch_bounds__(256, 2)
void gemm_fp16_kernel(const __half* __restrict__ Ah,
                      const __half* __restrict__ Al,
                      const __half* __restrict__ Bw,
                      const float* __restrict__ asrc,
                      const float* __restrict__ adst,
                      float* __restrict__ als4, float* __restrict__ ald4,
                      float* __restrict__ C, int M, int N, int K, int Nn) {
    constexpr int BK = 16;
    constexpr int AP = GEMM_AP;
    extern __shared__ __half sm[];
    __shared__ float s_as[128], s_ad[128];

    int tid  = threadIdx.x;
    int wid  = tid >> 5;
    int lane = tid & 31;
    int wm0  = (wid >> 1) * 32;         // 4x2 warp grid, warp tile 32x64
    int wn0  = (wid & 1) * 64;
    int g    = lane >> 2;
    int tg   = lane & 3;
    int m0   = blockIdx.y * 128;
    int n0   = blockIdx.x * 128;

    if (tid < 128) {
        s_as[tid] = asrc[n0 + tid];
        s_ad[tid] = adst[n0 + tid];
    }

    float acc[2][8][4];
#pragma unroll
    for (int mt = 0; mt < 2; mt++)
#pragma unroll
        for (int nt = 0; nt < 8; nt++)
#pragma unroll
            for (int j = 0; j < 4; j++) acc[mt][nt][j] = 0.f;

    int a_off = (wm0 + (lane & 15)) * AP + ((lane >> 4) << 3);
    int bq = lane >> 3, br = lane & 7;
    int b_off = (wn0 + ((bq >> 1) << 3) + br) * AP + ((bq & 1) << 3);

    int r0 = tid >> 1, s0g = tid & 1;
    unsigned sz0a = (m0 + r0 < M) ? 16u : 0u;
    size_t ar0 = (size_t)min(m0 + r0, M - 1) * K + s0g * 8;
    size_t br0 = (size_t)(n0 + r0) * K + s0g * 8;
    unsigned d0 = (unsigned)(r0 * 48 + s0g * 16);

    unsigned smb = (unsigned)__cvta_generic_to_shared(sm);

    auto stage = [&](int buf, int koff) {
        unsigned b = smb + buf * GEMM_BUFB;
        CPA16(b + 0 * GEMM_ARRB + d0, Ah + ar0 + koff, sz0a);
        CPA16(b + 1 * GEMM_ARRB + d0, Al + ar0 + koff, sz0a);
        CPA16(b + 2 * GEMM_ARRB + d0, Bw + br0 + koff, 16u);
        CPA_COMMIT();
    };

    int nk = K / BK;
    stage(0, 0);
    stage(1, BK);

    for (int t = 0; t < nk; ++t) {
        CPA_WAIT1();
        __syncthreads();
        if (t + 2 < nk) stage((t + 2) % 3, (t + 2) * BK);

        unsigned abase = smb + (t % 3) * GEMM_BUFB;
        unsigned ah[2][4], alr[2][4];
#pragma unroll
        for (int mt = 0; mt < 2; mt++) {
            LDSM4(ah[mt],  abase + 0 * GEMM_ARRB + (a_off + mt * 16 * AP) * 2);
            LDSM4(alr[mt], abase + 1 * GEMM_ARRB + (a_off + mt * 16 * AP) * 2);
        }
#pragma unroll
        for (int half = 0; half < 2; half++) {
            unsigned bf[2][4];
#pragma unroll
            for (int p = 0; p < 2; p++) {
                unsigned boff = (b_off + (half * 32 + p * 16) * AP) * 2;
                LDSM4(bf[p], abase + 2 * GEMM_ARRB + boff);
            }
#pragma unroll
            for (int mt = 0; mt < 2; mt++)
#pragma unroll
                for (int ntl = 0; ntl < 4; ntl++) {
                    int nt = half * 4 + ntl;
                    MMA16(acc[mt][nt], ah[mt],  &bf[ntl >> 1][(ntl & 1) * 2]);
                    MMA16(acc[mt][nt], alr[mt], &bf[ntl >> 1][(ntl & 1) * 2]);
                }
        }
    }
    CPA_WAIT0();

    // epilogue: store C + fused partial attention-logit dots
#pragma unroll
    for (int mt = 0; mt < 2; mt++) {
        int r = m0 + wm0 + mt * 16 + g;
        float ps0 = 0.f, pd0 = 0.f, ps1 = 0.f, pd1 = 0.f;
#pragma unroll
        for (int nt = 0; nt < 8; nt++) {
            int colL = wn0 + nt * 8 + 2 * tg;
            int col = n0 + colL;
            if (r < M)
                *(float2*)(C + (size_t)r * N + col) =
                    make_float2(acc[mt][nt][0], acc[mt][nt][1]);
            if (r + 8 < M)
                *(float2*)(C + (size_t)(r + 8) * N + col) =
                    make_float2(acc[mt][nt][2], acc[mt][nt][3]);
            float a0 = s_as[colL], a1 = s_as[colL + 1];
            float d0v = s_ad[colL], d1v = s_ad[colL + 1];
            ps0 += acc[mt][nt][0] * a0 + acc[mt][nt][1] * a1;
            pd0 += acc[mt][nt][0] * d0v + acc[mt][nt][1] * d1v;
            ps1 += acc[mt][nt][2] * a0 + acc[mt][nt][3] * a1;
            pd1 += acc[mt][nt][2] * d0v + acc[mt][nt][3] * d1v;
        }
#pragma unroll
        for (int o = 1; o < 4; o <<= 1) {
            ps0 += __shfl_xor_sync(0xffffffffu, ps0, o);
            pd0 += __shfl_xor_sync(0xffffffffu, pd0, o);
            ps1 += __shfl_xor_sync(0xffffffffu, ps1, o);
            pd1 += __shfl_xor_sync(0xffffffffu, pd1, o);
        }
        if (tg == 0) {
            if (r < M) {
                int v = r % Nn, b = r / Nn;
                atomicAdd(&als4[v * 4 + b], ps0);
                atomicAdd(&ald4[v * 4 + b], pd0);
            }
            if (r + 8 < M) {
                int v = (r + 8) % Nn, b = (r + 8) / Nn;
                atomicAdd(&als4[v * 4 + b], ps1);
                atomicAdd(&ald4[v * 4 + b], pd1);
            }
        }
    }
}

// ---------------- softmax aggregation: one block per node, ALL 4 batches
// Pass 1 loads ONE float4 of logits per edge (batch-transposed als4).
// Gather: two edge-quads per thread per iteration (8 LDG.128 in flight).
template <int F, bool SPLIT>
__global__ __launch_bounds__(F)
void agg4_kernel(const float* __restrict__ h, const float* __restrict__ als4,
                 const float* __restrict__ ald4, const float* __restrict__ bias,
                 float* __restrict__ out,
                 __half* __restrict__ outh, __half* __restrict__ outl,
                 int Nn) {
    constexpr int NW = F / 32;
    constexpr int FQ = F / 4;
    __shared__ float  se[BBMAX][DEGCAP + 8];   // logits -> exp weights (in place)
    __shared__ int    ssrc[DEGCAP + 8];
    __shared__ float  sredm[BBMAX][NW];
    __shared__ float  sbc[BBMAX];
    __shared__ float4 sred4[BBMAX][4][FQ];

    int v    = blockIdx.x;
    int tid  = threadIdx.x;
    int lane = tid & 31;
    int w    = tid >> 5;
    int begin = v * DEGCAP;
    int deg   = g_count[v];

    float4 adv = *(const float4*)(ald4 + v * 4);
    float aldv[BBMAX] = {adv.x, adv.y, adv.z, adv.w};

    // pass 1: stage srcs + logits (one float4 per edge), track per-thread max
    float lm[BBMAX];
#pragma unroll
    for (int b = 0; b < BBMAX; b++) lm[b] = -1e30f;
    for (int j = tid; j < deg; j += F) {
        int s = g_esrc[begin + j];
        ssrc[j] = s;
        float4 av = *(const float4*)(als4 + s * 4);
        float ev[BBMAX] = {av.x, av.y, av.z, av.w};
#pragma unroll
        for (int b = 0; b < BBMAX; b++) {
            float e = ev[b] + aldv[b];
            e = (e < 0.f) ? 0.2f * e : e;
            se[b][j] = e;
            lm[b] = fmaxf(lm[b], e);
        }
    }
    if (tid < 8) {                      // pad to multiple of 8
        int j = deg + tid;
        ssrc[j] = 0;
#pragma unroll
        for (int b = 0; b < BBMAX; b++) se[b][j] = -1e30f;
    }

    // combined block max reduce (4 batches at once)
#pragma unroll
    for (int b = 0; b < BBMAX; b++)
#pragma unroll
        for (int o = 16; o; o >>= 1)
            lm[b] = fmaxf(lm[b], __shfl_xor_sync(0xffffffffu, lm[b], o));
    if (!lane)
#pragma unroll
        for (int b = 0; b < BBMAX; b++) sredm[b][w] = lm[b];
    __syncthreads();
    if (w == 0) {
#pragma unroll
        for (int b = 0; b < BBMAX; b++) {
            float x = (lane < NW) ? sredm[b][lane] : -1e30f;
#pragma unroll
            for (int o = 16; o; o >>= 1)
                x = fmaxf(x, __shfl_xor_sync(0xffffffffu, x, o));
            if (!lane) sbc[b] = x;
        }
    }
    __syncthreads();
    float mb[BBMAX];
#pragma unroll
    for (int b = 0; b < BBMAX; b++) mb[b] = sbc[b];
    __syncthreads();                    // sbc reused below

    // exp in place + combined sum reduce
    float ls[BBMAX];
#pragma unroll
    for (int b = 0; b < BBMAX; b++) ls[b] = 0.f;
    for (int j = tid; j < deg; j += F) {
#pragma unroll
        for (int b = 0; b < BBMAX; b++) {
            float ex = __expf(se[b][j] - mb[b]);
            se[b][j] = ex;
            ls[b] += ex;
        }
    }
    if (tid < 8) {
        int j = deg + tid;
#pragma unroll
        for (int b = 0; b < BBMAX; b++) se[b][j] = 0.f;
    }
#pragma unroll
    for (int b = 0; b < BBMAX; b++)
#pragma unroll
        for (int o = 16; o; o >>= 1)
            ls[b] += __shfl_xor_sync(0xffffffffu, ls[b], o);
    if (!lane)
#pragma unroll
        for (int b = 0; b < BBMAX; b++) sredm[b][w] = ls[b];
    __syncthreads();
    if (w == 0) {
#pragma unroll
        for (int b = 0; b < BBMAX; b++) {
            float x = (lane < NW) ? sredm[b][lane] : 0.f;
#pragma unroll
            for (int o = 16; o; o >>= 1)
                x += __shfl_xor_sync(0xffffffffu, x, o);
            if (!lane) sbc[b] = x;
        }
    }
    __syncthreads();
    float inv[BBMAX];
#pragma unroll
    for (int b = 0; b < BBMAX; b++) inv[b] = 1.f / (sbc[b] + 1e-16f);

    // gather: two edge-quads per thread per iteration (j0+eg, j0+eg+4)
    int eg = tid / FQ;
    int fq = tid % FQ;
    float4 a[BBMAX];
#pragma unroll
    for (int b = 0; b < BBMAX; b++) a[b] = make_float4(0.f, 0.f, 0.f, 0.f);
    for (int j0 = 0; j0 < deg; j0 += 8) {
        int j  = j0 + eg;
        int j2 = j0 + eg + 4;
        int s  = ssrc[j];
        int s2 = ssrc[j2];
#pragma unroll
        for (int b = 0; b < BBMAX; b++) {
            float wj  = se[b][j];
            float wj2 = se[b][j2];
            float4 hv  = *(const float4*)(h + (size_t)(b * Nn + s)  * F + fq * 4);
            float4 hv2 = *(const float4*)(h + (size_t)(b * Nn + s2) * F + fq * 4);
            a[b].x += wj * hv.x + wj2 * hv2.x;
            a[b].y += wj * hv.y + wj2 * hv2.y;
            a[b].z += wj * hv.z + wj2 * hv2.z;
            a[b].w += wj * hv.w + wj2 * hv2.w;
        }
    }
#pragma unroll
    for (int b = 0; b < BBMAX; b++) sred4[b][eg][fq] = a[b];
    __syncthreads();

    int q = tid >> 2, c = tid & 3;
#pragma unroll
    for (int b = 0; b < BBMAX; b++) {
        float r = ((const float*)&sred4[b][0][q])[c] + ((const float*)&sred4[b][1][q])[c] +
                  ((const float*)&sred4[b][2][q])[c] + ((const float*)&sred4[b][3][q])[c];
        r = r * inv[b] + bias[tid];
        r = r > 0.f ? r : 0.f;
        size_t oi = (size_t)(b * Nn + v) * F + tid;
        if (SPLIT) {
            __half hi = __float2half(r);
            __half lo = __float2half(r - __half2float(hi));
            outh[oi] = hi;
            outl[oi] = lo;
        } else {
            out[oi] = r;
        }
    }
}

// ---------------- launch ----------------------------------------------
extern "C" void kernel_launch(void* const* d_in, const int* in_sizes, int n_in,
                              void* d_out, int out_size) {
    const float* x     = (const float*)d_in[0];
    const void*  edges = d_in[1];
    const float* W0    = (const float*)d_in[2];
    const float* b0    = (const float*)d_in[3];
    const float* asrc0 = (const float*)d_in[4];
    const float* adst0 = (const float*)d_in[5];
    const float* W1    = (const float*)d_in[6];
    const float* b1    = (const float*)d_in[7];
    const float* asrc1 = (const float*)d_in[8];
    const float* adst1 = (const float*)d_in[9];
    float* out = (float*)d_out;

    int F1 = in_sizes[3];            // 256
    int F0 = in_sizes[2] / F1;       // 256
    int F2 = in_sizes[7];            // 128
    int E  = in_sizes[1] / 2;        // 320000
    int M  = in_sizes[0] / F0;       // B*N = 40000
    int Nn = NN;                     // 10000
    int E2 = E + Nn;

    float *p_h0, *p_h1, *p_als4a, *p_ald4a, *p_als4b, *p_ald4b;
    __half *p_xh, *p_xl, *p_hidh, *p_hidl, *p_w0, *p_w1;
    cudaGetSymbolAddress((void**)&p_h0,    g_h0);
    cudaGetSymbolAddress((void**)&p_h1,    g_h1);
    cudaGetSymbolAddress((void**)&p_als4a, g_als4a);
    cudaGetSymbolAddress((void**)&p_ald4a, g_ald4a);
    cudaGetSymbolAddress((void**)&p_als4b, g_als4b);
    cudaGetSymbolAddress((void**)&p_ald4b, g_ald4b);
    cudaGetSymbolAddress((void**)&p_xh,    g_xh);
    cudaGetSymbolAddress((void**)&p_xl,    g_xl);
    cudaGetSymbolAddress((void**)&p_hidh,  g_hidh);
    cudaGetSymbolAddress((void**)&p_hidl,  g_hidl);
    cudaGetSymbolAddress((void**)&p_w0,    g_w0);
    cudaGetSymbolAddress((void**)&p_w1,    g_w1);

    cudaFuncSetAttribute(gemm_fp16_kernel,
                         cudaFuncAttributeMaxDynamicSharedMemorySize, GEMM_SMEM);

    int mtiles = (M + 127) / 128;
    int n0q = M * F0 / 4, n1q = F1 * F0 / 4, n2q = F2 * F1 / 4;

    // (0) fused splits, (1) zeros+detect, (2) CSR build, (3) GEMM0 [profiled]
    split3_kernel<<<(n0q + n1q + n2q + 255) / 256, 256>>>(
        x, p_xh, p_xl, n0q, W0, p_w0, n1q, W1, p_w1, n2q);
    zerodetect_kernel<<<(Nn * 4 + 255) / 256, 256>>>((const unsigned int*)edges, Nn);
    convert_scatter_kernel<<<(E2 + 255) / 256, 256>>>(edges, E, Nn);

    gemm_fp16_kernel<<<dim3(F1 / 128, mtiles), 256, GEMM_SMEM>>>(
        p_xh, p_xl, p_w0, asrc0, adst0, p_als4a, p_ald4a, p_h0, M, F1, F0, Nn);
    agg4_kernel<256, true><<<Nn, 256>>>(p_h0, p_als4a, p_ald4a, b0,
                                        nullptr, p_hidh, p_hidl, Nn);

    gemm_fp16_kernel<<<dim3(F2 / 128, mtiles), 256, GEMM_SMEM>>>(
        p_hidh, p_hidl, p_w1, asrc1, adst1, p_als4b, p_ald4b, p_h1, M, F2, F1, Nn);
    agg4_kernel<128, false><<<Nn, 128>>>(p_h1, p_als4b, p_ald4b, b1,
                                         out, nullptr, nullptr, Nn);
}

// round 15
// speedup vs baseline: 1.5429x; 1.1702x over previous
#include <cuda_runtime.h>
#include <cuda_fp16.h>
#include <cstdint>

// ---------------- problem constants (registry shapes) ----------------
#define NN      10000          // nodes per graph
#define EMAXE   320000         // edges (without self loops)
#define E2MAX   (EMAXE + NN)   // + self loops
#define BBMAX   4              // batch
#define DEGCAP  128            // padded-CSR capacity (max degree ~60 => 12 sigma safe)

// ---------------- device scratch (no allocations allowed) -------------
__device__ int   g_esrc[NN * DEGCAP];   // padded CSR: src per slot
__device__ int   g_count[NN];
__device__ int   g_is64;
__device__ float g_h0 [BBMAX * NN * 256];   // layer0 pre-attention features (fp32)
__device__ float g_h1 [BBMAX * NN * 128];   // layer1 pre-attention features (fp32)
__device__ float g_als4a[NN * 4];           // batch-transposed attention logits
__device__ float g_ald4a[NN * 4];
__device__ float g_als4b[NN * 4];
__device__ float g_ald4b[NN * 4];
// fp16 operands: x split hi/lo (exact to ~2^-22), W single fp16 (err 2^-12)
__device__ __half g_xh [BBMAX * NN * 256];
__device__ __half g_xl [BBMAX * NN * 256];
__device__ __half g_hidh[BBMAX * NN * 256];  // layer0 output, split
__device__ __half g_hidl[BBMAX * NN * 256];
__device__ __half g_w0 [256 * 256];
__device__ __half g_w1 [128 * 256];

// ---------------- fused preprocessing: zeros + detect + splits ---------
// index space: [0, Nn*4) zero logit accumulators (+counts for i<Nn),
//              then split x (n0), W0 (n1), W1 (n2) quads.
__global__ void prep_kernel(const unsigned int* __restrict__ w, int Nn,
                            const float* __restrict__ s0, __half* h0p, __half* l0p, int n0,
                            const float* __restrict__ s1, __half* h1p, int n1,
                            const float* __restrict__ s2, __half* h2p, int n2) {
    int i = blockIdx.x * blockDim.x + threadIdx.x;
    if (blockIdx.x == 0 && threadIdx.x == 0) {
        int ok = 1;
        for (int k = 1; k < 256; k += 2) {
            if (w[k] != 0u) { ok = 0; break; }
        }
        g_is64 = ok;
    }
    if (i < Nn * 4) {
        if (i < Nn) g_count[i] = 0;
        g_als4a[i] = 0.f;
        g_ald4a[i] = 0.f;
        g_als4b[i] = 0.f;
        g_ald4b[i] = 0.f;
        return;
    }
    i -= Nn * 4;
    if (i < n0) {
        float4 v = ((const float4*)s0)[i];
        float f[4] = {v.x, v.y, v.z, v.w};
        __half h[4], l[4];
#pragma unroll
        for (int q = 0; q < 4; q++) {
            h[q] = __float2half(f[q]);
            l[q] = __float2half(f[q] - __half2float(h[q]));
        }
        ((uint2*)h0p)[i] = *(uint2*)h;
        ((uint2*)l0p)[i] = *(uint2*)l;
        return;
    }
    i -= n0;
    const float* src; __half* ph;
    if (i < n1)              { src = s1; ph = h1p; }
    else if ((i -= n1) < n2) { src = s2; ph = h2p; }
    else return;
    float4 v = ((const float4*)src)[i];
    __half h[4] = {__float2half(v.x), __float2half(v.y),
                   __float2half(v.z), __float2half(v.w)};
    ((uint2*)ph)[i] = *(uint2*)h;
}

// one-pass padded-CSR build (incl. self loops)
__global__ void convert_scatter_kernel(const void* __restrict__ edges, int E, int Nn) {
    int i = blockIdx.x * blockDim.x + threadIdx.x;
    int E2 = E + Nn;
    if (i >= E2) return;
    int s, d;
    if (i < E) {
        if (g_is64) {
            const long long* p = (const long long*)edges;
            s = (int)p[i];
            d = (int)p[E + i];
        } else {
            const int* p = (const int*)edges;
            s = p[i];
            d = p[E + i];
        }
    } else {
        s = d = i - E;
    }
    int pos = atomicAdd(&g_count[d], 1);
    g_esrc[d * DEGCAP + pos] = s;
}

// ---------------- fp16 two-term tensor-core GEMM + fused al ------------
#define MMA16(c, a, b)                                                        \
    asm volatile(                                                             \
        "mma.sync.aligned.m16n8k16.row.col.f32.f16.f16.f32 "                  \
        "{%0,%1,%2,%3},{%4,%5,%6,%7},{%8,%9},{%0,%1,%2,%3};"                  \
        : "+f"((c)[0]), "+f"((c)[1]), "+f"((c)[2]), "+f"((c)[3])              \
        : "r"((a)[0]), "r"((a)[1]), "r"((a)[2]), "r"((a)[3]),                 \
          "r"((b)[0]), "r"((b)[1]))

#define LDSM4(R, addr)                                                        \
    asm volatile(                                                             \
        "ldmatrix.sync.aligned.m8n8.x4.shared.b16 {%0,%1,%2,%3}, [%4];"       \
        : "=r"((R)[0]), "=r"((R)[1]), "=r"((R)[2]), "=r"((R)[3])              \
        : "r"(addr))

#define CPA16(dst, src, sz)                                                   \
    asm volatile("cp.async.cg.shared.global [%0], [%1], 16, %2;"              \
                 :: "r"(dst), "l"(src), "r"(sz) : "memory")
#define CPA_COMMIT() asm volatile("cp.async.commit_group;" ::: "memory")
#define CPA_WAIT1()  asm volatile("cp.async.wait_group 1;" ::: "memory")
#define CPA_WAIT0()  asm volatile("cp.async.wait_group 0;" ::: "memory")

#define GEMM_AP    24
#define GEMM_ARRB  (128 * GEMM_AP * 2)
#define GEMM_BUFB  (3 * GEMM_ARRB)
#define GEMM_SMEM  (3 * GEMM_BUFB)

__global__ __launch_bounds__(256, 2)
void gemm_fp16_kernel(const __half* __restrict__ Ah,
                      const __half* __restrict__ Al,
                      const __half* __restrict__ Bw,
                      const float* __restrict__ asrc,
                      const float* __restrict__ adst,
                      float* __restrict__ als4, float* __restrict__ ald4,
                      float* __restrict__ C, int M, int N, int K, int Nn) {
    constexpr int BK = 16;
    constexpr int AP = GEMM_AP;
    extern __shared__ __half sm[];
    __shared__ float s_as[128], s_ad[128];

    int tid  = threadIdx.x;
    int wid  = tid >> 5;
    int lane = tid & 31;
    int wm0  = (wid >> 1) * 32;
    int wn0  = (wid & 1) * 64;
    int g    = lane >> 2;
    int tg   = lane & 3;
    int m0   = blockIdx.y * 128;
    int n0   = blockIdx.x * 128;

    if (tid < 128) {
        s_as[tid] = asrc[n0 + tid];
        s_ad[tid] = adst[n0 + tid];
    }

    float acc[2][8][4];
#pragma unroll
    for (int mt = 0; mt < 2; mt++)
#pragma unroll
        for (int nt = 0; nt < 8; nt++)
#pragma unroll
            for (int j = 0; j < 4; j++) acc[mt][nt][j] = 0.f;

    int a_off = (wm0 + (lane & 15)) * AP + ((lane >> 4) << 3);
    int bq = lane >> 3, br = lane & 7;
    int b_off = (wn0 + ((bq >> 1) << 3) + br) * AP + ((bq & 1) << 3);

    int r0 = tid >> 1, s0g = tid & 1;
    unsigned sz0a = (m0 + r0 < M) ? 16u : 0u;
    size_t ar0 = (size_t)min(m0 + r0, M - 1) * K + s0g * 8;
    size_t br0 = (size_t)(n0 + r0) * K + s0g * 8;
    unsigned d0 = (unsigned)(r0 * 48 + s0g * 16);

    unsigned smb = (unsigned)__cvta_generic_to_shared(sm);

    auto stage = [&](int buf, int koff) {
        unsigned b = smb + buf * GEMM_BUFB;
        CPA16(b + 0 * GEMM_ARRB + d0, Ah + ar0 + koff, sz0a);
        CPA16(b + 1 * GEMM_ARRB + d0, Al + ar0 + koff, sz0a);
        CPA16(b + 2 * GEMM_ARRB + d0, Bw + br0 + koff, 16u);
        CPA_COMMIT();
    };

    int nk = K / BK;
    stage(0, 0);
    stage(1, BK);

    for (int t = 0; t < nk; ++t) {
        CPA_WAIT1();
        __syncthreads();
        if (t + 2 < nk) stage((t + 2) % 3, (t + 2) * BK);

        unsigned abase = smb + (t % 3) * GEMM_BUFB;
        unsigned ah[2][4], alr[2][4];
#pragma unroll
        for (int mt = 0; mt < 2; mt++) {
            LDSM4(ah[mt],  abase + 0 * GEMM_ARRB + (a_off + mt * 16 * AP) * 2);
            LDSM4(alr[mt], abase + 1 * GEMM_ARRB + (a_off + mt * 16 * AP) * 2);
        }
#pragma unroll
        for (int half = 0; half < 2; half++) {
            unsigned bf[2][4];
#pragma unroll
            for (int p = 0; p < 2; p++) {
                unsigned boff = (b_off + (half * 32 + p * 16) * AP) * 2;
                LDSM4(bf[p], abase + 2 * GEMM_ARRB + boff);
            }
#pragma unroll
            for (int mt = 0; mt < 2; mt++)
#pragma unroll
                for (int ntl = 0; ntl < 4; ntl++) {
                    int nt = half * 4 + ntl;
                    MMA16(acc[mt][nt], ah[mt],  &bf[ntl >> 1][(ntl & 1) * 2]);
                    MMA16(acc[mt][nt], alr[mt], &bf[ntl >> 1][(ntl & 1) * 2]);
                }
        }
    }
    CPA_WAIT0();

    // epilogue: store C + fused partial attention-logit dots
#pragma unroll
    for (int mt = 0; mt < 2; mt++) {
        int r = m0 + wm0 + mt * 16 + g;
        float ps0 = 0.f, pd0 = 0.f, ps1 = 0.f, pd1 = 0.f;
#pragma unroll
        for (int nt = 0; nt < 8; nt++) {
            int colL = wn0 + nt * 8 + 2 * tg;
            int col = n0 + colL;
            if (r < M)
                *(float2*)(C + (size_t)r * N + col) =
                    make_float2(acc[mt][nt][0], acc[mt][nt][1]);
            if (r + 8 < M)
                *(float2*)(C + (size_t)(r + 8) * N + col) =
                    make_float2(acc[mt][nt][2], acc[mt][nt][3]);
            float a0 = s_as[colL], a1 = s_as[colL + 1];
            float d0v = s_ad[colL], d1v = s_ad[colL + 1];
            ps0 += acc[mt][nt][0] * a0 + acc[mt][nt][1] * a1;
            pd0 += acc[mt][nt][0] * d0v + acc[mt][nt][1] * d1v;
            ps1 += acc[mt][nt][2] * a0 + acc[mt][nt][3] * a1;
            pd1 += acc[mt][nt][2] * d0v + acc[mt][nt][3] * d1v;
        }
#pragma unroll
        for (int o = 1; o < 4; o <<= 1) {
            ps0 += __shfl_xor_sync(0xffffffffu, ps0, o);
            pd0 += __shfl_xor_sync(0xffffffffu, pd0, o);
            ps1 += __shfl_xor_sync(0xffffffffu, ps1, o);
            pd1 += __shfl_xor_sync(0xffffffffu, pd1, o);
        }
        if (tg == 0) {
            if (r < M) {
                int v = r % Nn, b = r / Nn;
                atomicAdd(&als4[v * 4 + b], ps0);
                atomicAdd(&ald4[v * 4 + b], pd0);
            }
            if (r + 8 < M) {
                int v = (r + 8) % Nn, b = (r + 8) / Nn;
                atomicAdd(&als4[v * 4 + b], ps1);
                atomicAdd(&ald4[v * 4 + b], pd1);
            }
        }
    }
}

// ---------------- softmax aggregation: one block per node, ALL 4 batches
// Softmax phase: warp b owns batch b — logits in registers, shuffle-only
// max/sum, normalization folded into stored weight. ONE deg-pass, ONE
// barrier before the gather. Gather as R13 (2 edge-quads/thread/iter).
template <int F, bool SPLIT>
__global__ __launch_bounds__(F)
void agg4_kernel(const float* __restrict__ h, const float* __restrict__ als4,
                 const float* __restrict__ ald4, const float* __restrict__ bias,
                 float* __restrict__ out,
                 __half* __restrict__ outh, __half* __restrict__ outl,
                 int Nn) {
    constexpr int FQ = F / 4;
    __shared__ float  se[BBMAX][DEGCAP + 8];   // normalized softmax weights
    __shared__ int    ssrc[DEGCAP + 8];
    __shared__ float4 sred4[BBMAX][4][FQ];

    int v    = blockIdx.x;
    int tid  = threadIdx.x;
    int lane = tid & 31;
    int w    = tid >> 5;
    int begin = v * DEGCAP;
    int deg   = g_count[v];

    // ---- softmax phase: warp b = batch b (deg <= DEGCAP = 128 -> k <= 4)
    if (w < BBMAX) {
        int b = w;
        float aldv = ald4[v * 4 + b];
        float ev[4];
        float lm = -1e30f;
        int nk = 0;
        for (int j = lane; j < deg; j += 32, nk++) {
            int s = g_esrc[begin + j];
            if (b == 0) ssrc[j] = s;
            float e = als4[s * 4 + b] + aldv;
            e = (e < 0.f) ? 0.2f * e : e;
            ev[nk] = e;
            lm = fmaxf(lm, e);
        }
        if (b == 0 && lane < 8) ssrc[deg + lane] = 0;   // pad
#pragma unroll
        for (int o = 16; o; o >>= 1)
            lm = fmaxf(lm, __shfl_xor_sync(0xffffffffu, lm, o));
        float ls = 0.f;
#pragma unroll
        for (int k = 0; k < 4; k++) {
            if (k < nk) {
                float ex = __expf(ev[k] - lm);
                ev[k] = ex;
                ls += ex;
            }
        }
#pragma unroll
        for (int o = 16; o; o >>= 1)
            ls += __shfl_xor_sync(0xffffffffu, ls, o);
        float inv = 1.f / (ls + 1e-16f);
        {
            int k = 0;
            for (int j = lane; j < deg; j += 32, k++) se[b][j] = ev[k] * inv;
        }
        if (lane < 8) se[b][deg + lane] = 0.f;          // pad weights
    }
    __syncthreads();

    // ---- gather: two edge-quads per thread per iteration
    int eg = tid / FQ;
    int fq = tid % FQ;
    float4 a[BBMAX];
#pragma unroll
    for (int b = 0; b < BBMAX; b++) a[b] = make_float4(0.f, 0.f, 0.f, 0.f);
    for (int j0 = 0; j0 < deg; j0 += 8) {
        int j  = j0 + eg;
        int j2 = j0 + eg + 4;
        int s  = ssrc[j];
        int s2 = ssrc[j2];
#pragma unroll
        for (int b = 0; b < BBMAX; b++) {
            float wj  = se[b][j];
            float wj2 = se[b][j2];
            float4 hv  = *(const float4*)(h + (size_t)(b * Nn + s)  * F + fq * 4);
            float4 hv2 = *(const float4*)(h + (size_t)(b * Nn + s2) * F + fq * 4);
            a[b].x += wj * hv.x + wj2 * hv2.x;
            a[b].y += wj * hv.y + wj2 * hv2.y;
            a[b].z += wj * hv.z + wj2 * hv2.z;
            a[b].w += wj * hv.w + wj2 * hv2.w;
        }
    }
#pragma unroll
    for (int b = 0; b < BBMAX; b++) sred4[b][eg][fq] = a[b];
    __syncthreads();

    int q = tid >> 2, c = tid & 3;
#pragma unroll
    for (int b = 0; b < BBMAX; b++) {
        float r = ((const float*)&sred4[b][0][q])[c] + ((const float*)&sred4[b][1][q])[c] +
                  ((const float*)&sred4[b][2][q])[c] + ((const float*)&sred4[b][3][q])[c];
        r = r + bias[tid];              // weights already normalized
        r = r > 0.f ? r : 0.f;
        size_t oi = (size_t)(b * Nn + v) * F + tid;
        if (SPLIT) {
            __half hi = __float2half(r);
            __half lo = __float2half(r - __half2float(hi));
            outh[oi] = hi;
            outl[oi] = lo;
        } else {
            out[oi] = r;
        }
    }
}

// ---------------- launch ----------------------------------------------
extern "C" void kernel_launch(void* const* d_in, const int* in_sizes, int n_in,
                              void* d_out, int out_size) {
    const float* x     = (const float*)d_in[0];
    const void*  edges = d_in[1];
    const float* W0    = (const float*)d_in[2];
    const float* b0    = (const float*)d_in[3];
    const float* asrc0 = (const float*)d_in[4];
    const float* adst0 = (const float*)d_in[5];
    const float* W1    = (const float*)d_in[6];
    const float* b1    = (const float*)d_in[7];
    const float* asrc1 = (const float*)d_in[8];
    const float* adst1 = (const float*)d_in[9];
    float* out = (float*)d_out;

    int F1 = in_sizes[3];            // 256
    int F0 = in_sizes[2] / F1;       // 256
    int F2 = in_sizes[7];            // 128
    int E  = in_sizes[1] / 2;        // 320000
    int M  = in_sizes[0] / F0;       // B*N = 40000
    int Nn = NN;                     // 10000
    int E2 = E + Nn;

    float *p_h0, *p_h1, *p_als4a, *p_ald4a, *p_als4b, *p_ald4b;
    __half *p_xh, *p_xl, *p_hidh, *p_hidl, *p_w0, *p_w1;
    cudaGetSymbolAddress((void**)&p_h0,    g_h0);
    cudaGetSymbolAddress((void**)&p_h1,    g_h1);
    cudaGetSymbolAddress((void**)&p_als4a, g_als4a);
    cudaGetSymbolAddress((void**)&p_ald4a, g_ald4a);
    cudaGetSymbolAddress((void**)&p_als4b, g_als4b);
    cudaGetSymbolAddress((void**)&p_ald4b, g_ald4b);
    cudaGetSymbolAddress((void**)&p_xh,    g_xh);
    cudaGetSymbolAddress((void**)&p_xl,    g_xl);
    cudaGetSymbolAddress((void**)&p_hidh,  g_hidh);
    cudaGetSymbolAddress((void**)&p_hidl,  g_hidl);
    cudaGetSymbolAddress((void**)&p_w0,    g_w0);
    cudaGetSymbolAddress((void**)&p_w1,    g_w1);

    cudaFuncSetAttribute(gemm_fp16_kernel,
                         cudaFuncAttributeMaxDynamicSharedMemorySize, GEMM_SMEM);

    int mtiles = (M + 127) / 128;
    int n0q = M * F0 / 4, n1q = F1 * F0 / 4, n2q = F2 * F1 / 4;
    int nprep = Nn * 4 + n0q + n1q + n2q;

    // (0) fused prep, (1) CSR build, (2) GEMM0, (3) agg0 [profiled slot]
    prep_kernel<<<(nprep + 255) / 256, 256>>>(
        (const unsigned int*)edges, Nn,
        x, p_xh, p_xl, n0q, W0, p_w0, n1q, W1, p_w1, n2q);
    convert_scatter_kernel<<<(E2 + 255) / 256, 256>>>(edges, E, Nn);

    gemm_fp16_kernel<<<dim3(F1 / 128, mtiles), 256, GEMM_SMEM>>>(
        p_xh, p_xl, p_w0, asrc0, adst0, p_als4a, p_ald4a, p_h0, M, F1, F0, Nn);
    agg4_kernel<256, true><<<Nn, 256>>>(p_h0, p_als4a, p_ald4a, b0,
                                        nullptr, p_hidh, p_hidl, Nn);

    gemm_fp16_kernel<<<dim3(F2 / 128, mtiles), 256, GEMM_SMEM>>>(
        p_hidh, p_hidl, p_w1, asrc1, adst1, p_als4b, p_ald4b, p_h1, M, F2, F1, Nn);
    agg4_kernel<128, false><<<Nn, 128>>>(p_h1, p_als4b, p_ald4b, b1,
                                         out, nullptr, nullptr, Nn);
}

// round 16
// speedup vs baseline: 1.6512x; 1.0702x over previous
#include <cuda_runtime.h>
#include <cuda_fp16.h>
#include <cstdint>

// ---------------- problem constants (registry shapes) ----------------
#define NN      10000          // nodes per graph
#define EMAXE   320000         // edges (without self loops)
#define E2MAX   (EMAXE + NN)   // + self loops
#define BBMAX   4              // batch
#define DEGCAP  128            // padded-CSR capacity (max degree ~60 => 12 sigma safe)

// ---------------- device scratch (no allocations allowed) -------------
__device__ int   g_esrc[NN * DEGCAP];   // padded CSR: src per slot
__device__ int   g_count[NN];
__device__ int   g_is64;
__device__ __half g_h0[BBMAX * NN * 256];   // layer0 pre-attention features (fp16)
__device__ __half g_h1[BBMAX * NN * 128];   // layer1 pre-attention features (fp16)
__device__ float g_als4a[NN * 4];           // batch-transposed attention logits
__device__ float g_ald4a[NN * 4];
__device__ float g_als4b[NN * 4];
__device__ float g_ald4b[NN * 4];
// fp16 operands: x split hi/lo (exact to ~2^-22), W single fp16 (err 2^-12)
__device__ __half g_xh [BBMAX * NN * 256];
__device__ __half g_xl [BBMAX * NN * 256];
__device__ __half g_hidh[BBMAX * NN * 256];  // layer0 output, split
__device__ __half g_hidl[BBMAX * NN * 256];
__device__ __half g_w0 [256 * 256];
__device__ __half g_w1 [128 * 256];

// ---------------- fused preprocessing: zeros + detect + splits ---------
__global__ void prep_kernel(const unsigned int* __restrict__ w, int Nn,
                            const float* __restrict__ s0, __half* h0p, __half* l0p, int n0,
                            const float* __restrict__ s1, __half* h1p, int n1,
                            const float* __restrict__ s2, __half* h2p, int n2) {
    int i = blockIdx.x * blockDim.x + threadIdx.x;
    if (blockIdx.x == 0 && threadIdx.x == 0) {
        int ok = 1;
        for (int k = 1; k < 256; k += 2) {
            if (w[k] != 0u) { ok = 0; break; }
        }
        g_is64 = ok;
    }
    if (i < Nn * 4) {
        if (i < Nn) g_count[i] = 0;
        g_als4a[i] = 0.f;
        g_ald4a[i] = 0.f;
        g_als4b[i] = 0.f;
        g_ald4b[i] = 0.f;
        return;
    }
    i -= Nn * 4;
    if (i < n0) {
        float4 v = ((const float4*)s0)[i];
        float f[4] = {v.x, v.y, v.z, v.w};
        __half h[4], l[4];
#pragma unroll
        for (int q = 0; q < 4; q++) {
            h[q] = __float2half(f[q]);
            l[q] = __float2half(f[q] - __half2float(h[q]));
        }
        ((uint2*)h0p)[i] = *(uint2*)h;
        ((uint2*)l0p)[i] = *(uint2*)l;
        return;
    }
    i -= n0;
    const float* src; __half* ph;
    if (i < n1)              { src = s1; ph = h1p; }
    else if ((i -= n1) < n2) { src = s2; ph = h2p; }
    else return;
    float4 v = ((const float4*)src)[i];
    __half h[4] = {__float2half(v.x), __float2half(v.y),
                   __float2half(v.z), __float2half(v.w)};
    ((uint2*)ph)[i] = *(uint2*)h;
}

// one-pass padded-CSR build (incl. self loops)
__global__ void convert_scatter_kernel(const void* __restrict__ edges, int E, int Nn) {
    int i = blockIdx.x * blockDim.x + threadIdx.x;
    int E2 = E + Nn;
    if (i >= E2) return;
    int s, d;
    if (i < E) {
        if (g_is64) {
            const long long* p = (const long long*)edges;
            s = (int)p[i];
            d = (int)p[E + i];
        } else {
            const int* p = (const int*)edges;
            s = p[i];
            d = p[E + i];
        }
    } else {
        s = d = i - E;
    }
    int pos = atomicAdd(&g_count[d], 1);
    g_esrc[d * DEGCAP + pos] = s;
}

// ---------------- fp16 two-term tensor-core GEMM + fused al ------------
// C stored ONLY as fp16 (its sole consumer is the agg gather); attention
// logit dots computed from the fp32 accumulators in-register.
#define MMA16(c, a, b)                                                        \
    asm volatile(                                                             \
        "mma.sync.aligned.m16n8k16.row.col.f32.f16.f16.f32 "                  \
        "{%0,%1,%2,%3},{%4,%5,%6,%7},{%8,%9},{%0,%1,%2,%3};"                  \
        : "+f"((c)[0]), "+f"((c)[1]), "+f"((c)[2]), "+f"((c)[3])              \
        : "r"((a)[0]), "r"((a)[1]), "r"((a)[2]), "r"((a)[3]),                 \
          "r"((b)[0]), "r"((b)[1]))

#define LDSM4(R, addr)                                                        \
    asm volatile(                                                             \
        "ldmatrix.sync.aligned.m8n8.x4.shared.b16 {%0,%1,%2,%3}, [%4];"       \
        : "=r"((R)[0]), "=r"((R)[1]), "=r"((R)[2]), "=r"((R)[3])              \
        : "r"(addr))

#define CPA16(dst, src, sz)                                                   \
    asm volatile("cp.async.cg.shared.global [%0], [%1], 16, %2;"              \
                 :: "r"(dst), "l"(src), "r"(sz) : "memory")
#define CPA_COMMIT() asm volatile("cp.async.commit_group;" ::: "memory")
#define CPA_WAIT1()  asm volatile("cp.async.wait_group 1;" ::: "memory")
#define CPA_WAIT0()  asm volatile("cp.async.wait_group 0;" ::: "memory")

#define GEMM_AP    24
#define GEMM_ARRB  (128 * GEMM_AP * 2)
#define GEMM_BUFB  (3 * GEMM_ARRB)
#define GEMM_SMEM  (3 * GEMM_BUFB)

__global__ __launch_bounds__(256, 2)
void gemm_fp16_kernel(const __half* __restrict__ Ah,
                      const __half* __restrict__ Al,
                      const __half* __restrict__ Bw,
                      const float* __restrict__ asrc,
                      const float* __restrict__ adst,
                      float* __restrict__ als4, float* __restrict__ ald4,
                      __half* __restrict__ Cx, int M, int N, int K, int Nn) {
    constexpr int BK = 16;
    constexpr int AP = GEMM_AP;
    extern __shared__ __half sm[];
    __shared__ float s_as[128], s_ad[128];

    int tid  = threadIdx.x;
    int wid  = tid >> 5;
    int lane = tid & 31;
    int wm0  = (wid >> 1) * 32;
    int wn0  = (wid & 1) * 64;
    int g    = lane >> 2;
    int tg   = lane & 3;
    int m0   = blockIdx.y * 128;
    int n0   = blockIdx.x * 128;

    if (tid < 128) {
        s_as[tid] = asrc[n0 + tid];
        s_ad[tid] = adst[n0 + tid];
    }

    float acc[2][8][4];
#pragma unroll
    for (int mt = 0; mt < 2; mt++)
#pragma unroll
        for (int nt = 0; nt < 8; nt++)
#pragma unroll
            for (int j = 0; j < 4; j++) acc[mt][nt][j] = 0.f;

    int a_off = (wm0 + (lane & 15)) * AP + ((lane >> 4) << 3);
    int bq = lane >> 3, br = lane & 7;
    int b_off = (wn0 + ((bq >> 1) << 3) + br) * AP + ((bq & 1) << 3);

    int r0 = tid >> 1, s0g = tid & 1;
    unsigned sz0a = (m0 + r0 < M) ? 16u : 0u;
    size_t ar0 = (size_t)min(m0 + r0, M - 1) * K + s0g * 8;
    size_t br0 = (size_t)(n0 + r0) * K + s0g * 8;
    unsigned d0 = (unsigned)(r0 * 48 + s0g * 16);

    unsigned smb = (unsigned)__cvta_generic_to_shared(sm);

    auto stage = [&](int buf, int koff) {
        unsigned b = smb + buf * GEMM_BUFB;
        CPA16(b + 0 * GEMM_ARRB + d0, Ah + ar0 + koff, sz0a);
        CPA16(b + 1 * GEMM_ARRB + d0, Al + ar0 + koff, sz0a);
        CPA16(b + 2 * GEMM_ARRB + d0, Bw + br0 + koff, 16u);
        CPA_COMMIT();
    };

    int nk = K / BK;
    stage(0, 0);
    stage(1, BK);

    for (int t = 0; t < nk; ++t) {
        CPA_WAIT1();
        __syncthreads();
        if (t + 2 < nk) stage((t + 2) % 3, (t + 2) * BK);

        unsigned abase = smb + (t % 3) * GEMM_BUFB;
        unsigned ah[2][4], alr[2][4];
#pragma unroll
        for (int mt = 0; mt < 2; mt++) {
            LDSM4(ah[mt],  abase + 0 * GEMM_ARRB + (a_off + mt * 16 * AP) * 2);
            LDSM4(alr[mt], abase + 1 * GEMM_ARRB + (a_off + mt * 16 * AP) * 2);
        }
#pragma unroll
        for (int half = 0; half < 2; half++) {
            unsigned bf[2][4];
#pragma unroll
            for (int p = 0; p < 2; p++) {
                unsigned boff = (b_off + (half * 32 + p * 16) * AP) * 2;
                LDSM4(bf[p], abase + 2 * GEMM_ARRB + boff);
            }
#pragma unroll
            for (int mt = 0; mt < 2; mt++)
#pragma unroll
                for (int ntl = 0; ntl < 4; ntl++) {
                    int nt = half * 4 + ntl;
                    MMA16(acc[mt][nt], ah[mt],  &bf[ntl >> 1][(ntl & 1) * 2]);
                    MMA16(acc[mt][nt], alr[mt], &bf[ntl >> 1][(ntl & 1) * 2]);
                }
        }
    }
    CPA_WAIT0();

    // epilogue: fp16 h store + fused partial attention-logit dots
#pragma unroll
    for (int mt = 0; mt < 2; mt++) {
        int r = m0 + wm0 + mt * 16 + g;
        float ps0 = 0.f, pd0 = 0.f, ps1 = 0.f, pd1 = 0.f;
#pragma unroll
        for (int nt = 0; nt < 8; nt++) {
            int colL = wn0 + nt * 8 + 2 * tg;
            int col = n0 + colL;
            if (r < M)
                *(__half2*)(Cx + (size_t)r * N + col) =
                    __floats2half2_rn(acc[mt][nt][0], acc[mt][nt][1]);
            if (r + 8 < M)
                *(__half2*)(Cx + (size_t)(r + 8) * N + col) =
                    __floats2half2_rn(acc[mt][nt][2], acc[mt][nt][3]);
            float a0 = s_as[colL], a1 = s_as[colL + 1];
            float d0v = s_ad[colL], d1v = s_ad[colL + 1];
            ps0 += acc[mt][nt][0] * a0 + acc[mt][nt][1] * a1;
            pd0 += acc[mt][nt][0] * d0v + acc[mt][nt][1] * d1v;
            ps1 += acc[mt][nt][2] * a0 + acc[mt][nt][3] * a1;
            pd1 += acc[mt][nt][2] * d0v + acc[mt][nt][3] * d1v;
        }
#pragma unroll
        for (int o = 1; o < 4; o <<= 1) {
            ps0 += __shfl_xor_sync(0xffffffffu, ps0, o);
            pd0 += __shfl_xor_sync(0xffffffffu, pd0, o);
            ps1 += __shfl_xor_sync(0xffffffffu, ps1, o);
            pd1 += __shfl_xor_sync(0xffffffffu, pd1, o);
        }
        if (tg == 0) {
            if (r < M) {
                int v = r % Nn, b = r / Nn;
                atomicAdd(&als4[v * 4 + b], ps0);
                atomicAdd(&ald4[v * 4 + b], pd0);
            }
            if (r + 8 < M) {
                int v = (r + 8) % Nn, b = (r + 8) / Nn;
                atomicAdd(&als4[v * 4 + b], ps1);
                atomicAdd(&ald4[v * 4 + b], pd1);
            }
        }
    }
}

// ---------------- softmax aggregation: one block per node, ALL 4 batches
// Warp-per-batch softmax (registers + shuffles, normalized weights),
// fp16 gather (uint2 = 4 halves/thread), fp32 accumulate, STS128 reduce.
template <int F, bool SPLIT>
__global__ __launch_bounds__(F)
void agg4_kernel(const __half* __restrict__ h, const float* __restrict__ als4,
                 const float* __restrict__ ald4, const float* __restrict__ bias,
                 float* __restrict__ out,
                 __half* __restrict__ outh, __half* __restrict__ outl,
                 int Nn) {
    constexpr int FQ = F / 4;
    __shared__ float  se[BBMAX][DEGCAP + 8];   // normalized softmax weights
    __shared__ int    ssrc[DEGCAP + 8];
    __shared__ float4 sred4[BBMAX][4][FQ];

    int v    = blockIdx.x;
    int tid  = threadIdx.x;
    int lane = tid & 31;
    int w    = tid >> 5;
    int begin = v * DEGCAP;
    int deg   = g_count[v];

    // ---- softmax phase: warp b = batch b (deg <= 128 -> k <= 4)
    if (w < BBMAX) {
        int b = w;
        float aldv = ald4[v * 4 + b];
        float ev[4];
        float lm = -1e30f;
        int nk = 0;
        for (int j = lane; j < deg; j += 32, nk++) {
            int s = g_esrc[begin + j];
            if (b == 0) ssrc[j] = s;
            float e = als4[s * 4 + b] + aldv;
            e = (e < 0.f) ? 0.2f * e : e;
            ev[nk] = e;
            lm = fmaxf(lm, e);
        }
        if (b == 0 && lane < 8) ssrc[deg + lane] = 0;   // pad
#pragma unroll
        for (int o = 16; o; o >>= 1)
            lm = fmaxf(lm, __shfl_xor_sync(0xffffffffu, lm, o));
        float ls = 0.f;
#pragma unroll
        for (int k = 0; k < 4; k++) {
            if (k < nk) {
                float ex = __expf(ev[k] - lm);
                ev[k] = ex;
                ls += ex;
            }
        }
#pragma unroll
        for (int o = 16; o; o >>= 1)
            ls += __shfl_xor_sync(0xffffffffu, ls, o);
        float inv = 1.f / (ls + 1e-16f);
        {
            int k = 0;
            for (int j = lane; j < deg; j += 32, k++) se[b][j] = ev[k] * inv;
        }
        if (lane < 8) se[b][deg + lane] = 0.f;          // pad weights
    }
    __syncthreads();

    // ---- gather: fp16, two edge-quads per thread per iteration
    int eg = tid / FQ;
    int fq = tid % FQ;
    float4 a[BBMAX];
#pragma unroll
    for (int b = 0; b < BBMAX; b++) a[b] = make_float4(0.f, 0.f, 0.f, 0.f);
    for (int j0 = 0; j0 < deg; j0 += 8) {
        int j  = j0 + eg;
        int j2 = j0 + eg + 4;
        int s  = ssrc[j];
        int s2 = ssrc[j2];
#pragma unroll
        for (int b = 0; b < BBMAX; b++) {
            float wj  = se[b][j];
            float wj2 = se[b][j2];
            uint2 hv  = *(const uint2*)(h + (size_t)(b * Nn + s)  * F + fq * 4);
            uint2 hv2 = *(const uint2*)(h + (size_t)(b * Nn + s2) * F + fq * 4);
            float2 f0 = __half22float2(*(const __half2*)&hv.x);
            float2 f1 = __half22float2(*(const __half2*)&hv.y);
            float2 g0 = __half22float2(*(const __half2*)&hv2.x);
            float2 g1 = __half22float2(*(const __half2*)&hv2.y);
            a[b].x += wj * f0.x + wj2 * g0.x;
            a[b].y += wj * f0.y + wj2 * g0.y;
            a[b].z += wj * f1.x + wj2 * g1.x;
            a[b].w += wj * f1.y + wj2 * g1.y;
        }
    }
#pragma unroll
    for (int b = 0; b < BBMAX; b++) sred4[b][eg][fq] = a[b];
    __syncthreads();

    int q = tid >> 2, c = tid & 3;
#pragma unroll
    for (int b = 0; b < BBMAX; b++) {
        float r = ((const float*)&sred4[b][0][q])[c] + ((const float*)&sred4[b][1][q])[c] +
                  ((const float*)&sred4[b][2][q])[c] + ((const float*)&sred4[b][3][q])[c];
        r = r + bias[tid];              // weights already normalized
        r = r > 0.f ? r : 0.f;
        size_t oi = (size_t)(b * Nn + v) * F + tid;
        if (SPLIT) {
            __half hi = __float2half(r);
            __half lo = __float2half(r - __half2float(hi));
            outh[oi] = hi;
            outl[oi] = lo;
        } else {
            out[oi] = r;
        }
    }
}

// ---------------- launch ----------------------------------------------
extern "C" void kernel_launch(void* const* d_in, const int* in_sizes, int n_in,
                              void* d_out, int out_size) {
    const float* x     = (const float*)d_in[0];
    const void*  edges = d_in[1];
    const float* W0    = (const float*)d_in[2];
    const float* b0    = (const float*)d_in[3];
    const float* asrc0 = (const float*)d_in[4];
    const float* adst0 = (const float*)d_in[5];
    const float* W1    = (const float*)d_in[6];
    const float* b1    = (const float*)d_in[7];
    const float* asrc1 = (const float*)d_in[8];
    const float* adst1 = (const float*)d_in[9];
    float* out = (float*)d_out;

    int F1 = in_sizes[3];            // 256
    int F0 = in_sizes[2] / F1;       // 256
    int F2 = in_sizes[7];            // 128
    int E  = in_sizes[1] / 2;        // 320000
    int M  = in_sizes[0] / F0;       // B*N = 40000
    int Nn = NN;                     // 10000
    int E2 = E + Nn;

    float *p_als4a, *p_ald4a, *p_als4b, *p_ald4b;
    __half *p_h0, *p_h1, *p_xh, *p_xl, *p_hidh, *p_hidl, *p_w0, *p_w1;
    cudaGetSymbolAddress((void**)&p_h0,    g_h0);
    cudaGetSymbolAddress((void**)&p_h1,    g_h1);
    cudaGetSymbolAddress((void**)&p_als4a, g_als4a);
    cudaGetSymbolAddress((void**)&p_ald4a, g_ald4a);
    cudaGetSymbolAddress((void**)&p_als4b, g_als4b);
    cudaGetSymbolAddress((void**)&p_ald4b, g_ald4b);
    cudaGetSymbolAddress((void**)&p_xh,    g_xh);
    cudaGetSymbolAddress((void**)&p_xl,    g_xl);
    cudaGetSymbolAddress((void**)&p_hidh,  g_hidh);
    cudaGetSymbolAddress((void**)&p_hidl,  g_hidl);
    cudaGetSymbolAddress((void**)&p_w0,    g_w0);
    cudaGetSymbolAddress((void**)&p_w1,    g_w1);

    cudaFuncSetAttribute(gemm_fp16_kernel,
                         cudaFuncAttributeMaxDynamicSharedMemorySize, GEMM_SMEM);

    int mtiles = (M + 127) / 128;
    int n0q = M * F0 / 4, n1q = F1 * F0 / 4, n2q = F2 * F1 / 4;
    int nprep = Nn * 4 + n0q + n1q + n2q;

    // (0) fused prep, (1) CSR build, (2) GEMM0, (3) agg0 [profiled slot]
    prep_kernel<<<(nprep + 255) / 256, 256>>>(
        (const unsigned int*)edges, Nn,
        x, p_xh, p_xl, n0q, W0, p_w0, n1q, W1, p_w1, n2q);
    convert_scatter_kernel<<<(E2 + 255) / 256, 256>>>(edges, E, Nn);

    gemm_fp16_kernel<<<dim3(F1 / 128, mtiles), 256, GEMM_SMEM>>>(
        p_xh, p_xl, p_w0, asrc0, adst0, p_als4a, p_ald4a, p_h0, M, F1, F0, Nn);
    agg4_kernel<256, true><<<Nn, 256>>>(p_h0, p_als4a, p_ald4a, b0,
                                        nullptr, p_hidh, p_hidl, Nn);

    gemm_fp16_kernel<<<dim3(F2 / 128, mtiles), 256, GEMM_SMEM>>>(
        p_hidh, p_hidl, p_w1, asrc1, adst1, p_als4b, p_ald4b, p_h1, M, F2, F1, Nn);
    agg4_kernel<128, false><<<Nn, 128>>>(p_h1, p_als4b, p_ald4b, b1,
                                         out, nullptr, nullptr, Nn);
}